// round 3
// baseline (speedup 1.0000x reference)
#include <cuda_runtime.h>

#define HID   128
#define S     8
#define NWARP 12
#define NTHR  384

__device__ __forceinline__ float ftanh(float x) {
    float e = __expf(2.0f * x);
    return 1.0f - __fdividef(2.0f, e + 1.0f);
}

__device__ __forceinline__ unsigned long long ffma2(unsigned long long a,
                                                    unsigned long long b,
                                                    unsigned long long c) {
    unsigned long long d;
    asm("fma.rn.f32x2 %0, %1, %2, %3;" : "=l"(d) : "l"(a), "l"(b), "l"(c));
    return d;
}

__device__ __forceinline__ float hadd2(unsigned long long v) {
    float lo, hi;
    asm("mov.b64 {%0, %1}, %2;" : "=f"(lo), "=f"(hi) : "l"(v));
    return lo + hi;
}
__device__ __forceinline__ float lo2(unsigned long long v) {
    float lo, hi;
    asm("mov.b64 {%0, %1}, %2;" : "=f"(lo), "=f"(hi) : "l"(v));
    return lo;
}
__device__ __forceinline__ float hi2(unsigned long long v) {
    float lo, hi;
    asm("mov.b64 {%0, %1}, %2;" : "=f"(lo), "=f"(hi) : "l"(v));
    return hi;
}

__global__ void __launch_bounds__(NTHR, 1)
lnn_kernel(const float* __restrict__ X,
           const float* __restrict__ W1, const float* __restrict__ b1,
           const float* __restrict__ W2, const float* __restrict__ b2,
           const float* __restrict__ W3,
           float* __restrict__ out, int B)
{
    extern __shared__ float sm[];
    float* sW2F = sm;                  // [k][j-chunks swizzled]  (single copy)
    float* sW1  = sW2F + HID * HID;    // 4*128
    float* sb1  = sW1 + 4 * HID;
    float* sb2  = sb1 + HID;
    float* sW3  = sb2 + HID;
    float* bufs = sW3 + HID;           // per warp: h1b S*128 + g2dup S*256

    const int tid = threadIdx.x;

    // stage W2 transposed+swizzled: sW2F[k][chunk (j>>2)^(k>>2)][j&3] = W2[j][k]
    for (int idx = tid; idx < HID * HID; idx += NTHR) {
        const int j = idx >> 7, k = idx & 127;
        sW2F[k * HID + ((((j >> 2) ^ (k >> 2)) & 31) << 2) + (j & 3)] = W2[idx];
    }
    for (int idx = tid; idx < 4 * HID; idx += NTHR) sW1[idx] = W1[idx];
    for (int idx = tid; idx < HID; idx += NTHR) {
        sb1[idx] = b1[idx];
        sb2[idx] = b2[idx];
        sW3[idx] = W3[idx];
    }
    __syncthreads();

    const int warp = tid >> 5;
    const int lane = tid & 31;
    const int u0   = lane << 2;               // lane-owned unit rows u0..u0+3
    float* h1b   = bufs + warp * (S * HID + S * 2 * HID);  // [s][128]
    float* g2dup = h1b + S * HID;                          // [s][k] as (g,g) pairs

    const float* wF[4];
    #pragma unroll
    for (int r = 0; r < 4; r++) wF[r] = sW2F + (u0 + r) * HID;

    const int gw    = blockIdx.x * NWARP + warp;
    const int nwTot = gridDim.x * NWARP;

    for (int base = gw * S; base < B; base += nwTot * S) {
        float t1[S], t2[S], wv1[S], wv2[S];
        #pragma unroll
        for (int s = 0; s < S; s++) {
            const float4 x = reinterpret_cast<const float4*>(X)[base + s];
            t1[s] = x.x; t2[s] = x.y; wv1[s] = x.z; wv2[s] = x.w;
        }
        float s1[S], c1[S], s2[S], c2[S];
        #pragma unroll
        for (int s = 0; s < S; s++) {
            __sincosf(t1[s], &s1[s], &c1[s]);
            __sincosf(t2[s], &s2[s], &c2[s]);
        }

        // ---- layer 1 ----
        float h1r[S][4];
        #pragma unroll
        for (int r = 0; r < 4; r++) {
            const int u = u0 + r;
            const float a0 = sW1[u], a1 = sW1[HID + u];
            const float a2 = sW1[2 * HID + u], a3 = sW1[3 * HID + u];
            const float bb = sb1[u];
            #pragma unroll
            for (int s = 0; s < S; s++) {
                float z = bb;
                z = fmaf(s1[s], a0, z);
                z = fmaf(c1[s], a1, z);
                z = fmaf(s2[s], a2, z);
                z = fmaf(c2[s], a3, z);
                h1r[s][r] = ftanh(z);
            }
        }
        __syncwarp();
        #pragma unroll
        for (int s = 0; s < S; s++)
            *reinterpret_cast<float4*>(&h1b[s * HID + u0]) =
                make_float4(h1r[s][0], h1r[s][1], h1r[s][2], h1r[s][3]);
        __syncwarp();

        // ---- forward: z2[k] = sum_j h[j]*W2[j][k], pairs over j ----
        unsigned long long acc2[S][4];
        #pragma unroll
        for (int s = 0; s < S; s++)
            #pragma unroll
            for (int r = 0; r < 4; r++) acc2[s][r] = 0ull;

        for (int jc = 0; jc < 32; jc++) {
            const int off = ((jc ^ lane) & 31) << 2;
            ulonglong2 wvr[4];
            #pragma unroll
            for (int r = 0; r < 4; r++)
                wvr[r] = *reinterpret_cast<const ulonglong2*>(wF[r] + off);
            #pragma unroll
            for (int s = 0; s < S; s++) {
                const ulonglong2 hv =
                    *reinterpret_cast<const ulonglong2*>(&h1b[s * HID + (jc << 2)]);
                #pragma unroll
                for (int r = 0; r < 4; r++) {
                    acc2[s][r] = ffma2(hv.x, wvr[r].x, acc2[s][r]);
                    acc2[s][r] = ffma2(hv.y, wvr[r].y, acc2[s][r]);
                }
            }
        }

        // ---- g2[k] = W3[k]*(1-tanh(z2)^2), stored duplicated (g,g) ----
        __syncwarp();
        #pragma unroll
        for (int s = 0; s < S; s++) {
            float g[4];
            #pragma unroll
            for (int r = 0; r < 4; r++) {
                const float z = hadd2(acc2[s][r]) + sb2[u0 + r];
                const float t = ftanh(z);
                g[r] = sW3[u0 + r] * (1.0f - t * t);
            }
            float* dst = &g2dup[s * 2 * HID + (u0 << 1)];
            *reinterpret_cast<float4*>(dst)     = make_float4(g[0], g[0], g[1], g[1]);
            *reinterpret_cast<float4*>(dst + 4) = make_float4(g[2], g[2], g[3], g[3]);
        }
        __syncwarp();

        // ---- backward: g1pre[j] = sum_k W2[j][k]*g2[k], pairs over j ----
        // reuse sW2F rows (indexed by k), lane reads its own j-chunk per row
        unsigned long long gaccp[S][2];
        #pragma unroll
        for (int s = 0; s < S; s++) { gaccp[s][0] = 0ull; gaccp[s][1] = 0ull; }

        for (int kc = 0; kc < 32; kc++) {
            const int off = ((kc ^ lane) & 31) << 2;
            ulonglong2 wrow[4];
            #pragma unroll
            for (int q = 0; q < 4; q++)
                wrow[q] = *reinterpret_cast<const ulonglong2*>(
                    sW2F + ((kc << 2) + q) * HID + off);
            #pragma unroll
            for (int s = 0; s < S; s++) {
                const ulonglong2 gdA =
                    *reinterpret_cast<const ulonglong2*>(&g2dup[s * 2 * HID + (kc << 3)]);
                const ulonglong2 gdB =
                    *reinterpret_cast<const ulonglong2*>(&g2dup[s * 2 * HID + (kc << 3) + 4]);
                gaccp[s][0] = ffma2(gdA.x, wrow[0].x, gaccp[s][0]);
                gaccp[s][1] = ffma2(gdA.x, wrow[0].y, gaccp[s][1]);
                gaccp[s][0] = ffma2(gdA.y, wrow[1].x, gaccp[s][0]);
                gaccp[s][1] = ffma2(gdA.y, wrow[1].y, gaccp[s][1]);
                gaccp[s][0] = ffma2(gdB.x, wrow[2].x, gaccp[s][0]);
                gaccp[s][1] = ffma2(gdB.x, wrow[2].y, gaccp[s][1]);
                gaccp[s][0] = ffma2(gdB.y, wrow[3].x, gaccp[s][0]);
                gaccp[s][1] = ffma2(gdB.y, wrow[3].y, gaccp[s][1]);
            }
        }

        // ---- feature-gradient partials ----
        float pf[4][S];
        #pragma unroll
        for (int i = 0; i < 4; i++)
            #pragma unroll
            for (int s = 0; s < S; s++) pf[i][s] = 0.0f;

        #pragma unroll
        for (int r = 0; r < 4; r++) {
            const int j = u0 + r;
            const float a0 = sW1[j], a1 = sW1[HID + j];
            const float a2 = sW1[2 * HID + j], a3 = sW1[3 * HID + j];
            #pragma unroll
            for (int s = 0; s < S; s++) {
                const float pre = (r & 1) ? hi2(gaccp[s][r >> 1])
                                          : lo2(gaccp[s][r >> 1]);
                const float h   = h1r[s][r];
                const float g1  = (1.0f - h * h) * pre;
                pf[0][s] = fmaf(a0, g1, pf[0][s]);
                pf[1][s] = fmaf(a1, g1, pf[1][s]);
                pf[2][s] = fmaf(a2, g1, pf[2][s]);
                pf[3][s] = fmaf(a3, g1, pf[3][s]);
            }
        }

        #pragma unroll
        for (int off = 16; off > 0; off >>= 1)
            #pragma unroll
            for (int i = 0; i < 4; i++)
                #pragma unroll
                for (int s = 0; s < S; s++)
                    pf[i][s] += __shfl_xor_sync(0xffffffffu, pf[i][s], off);

        if (lane < S) {
            const int s = lane;
            const float w1v = wv1[s], w2v = wv2[s];
            const float sd = s1[s] * c2[s] - c1[s] * s2[s];
            const float cd = c1[s] * c2[s] + s1[s] * s2[s];
            const float dV1 = pf[0][s] * c1[s] - pf[1][s] * s1[s];
            const float dV2 = pf[2][s] * c2[s] - pf[3][s] * s2[s];
            const float dw  = w2v - w1v;
            const float rhs1 = -w1v * w2v * sd - dV1 - w2v * sd * dw;
            const float rhs2 =  w1v * w2v * sd - dV2 - w1v * sd * dw;
            const float det = 2.0f - cd * cd;
            const float inv = __fdividef(1.0f, det);
            const float q1 = (rhs1 - cd * rhs2) * inv;
            const float q2 = (2.0f * rhs2 - cd * rhs1) * inv;
            reinterpret_cast<float4*>(out)[base + s] =
                make_float4(w1v, w2v, q1, q2);
        }
    }
}

extern "C" void kernel_launch(void* const* d_in, const int* in_sizes, int n_in,
                              void* d_out, int out_size)
{
    const float* X  = (const float*)d_in[0];
    const float* W1 = (const float*)d_in[1];
    const float* b1 = (const float*)d_in[2];
    const float* W2 = (const float*)d_in[3];
    const float* b2 = (const float*)d_in[4];
    const float* W3 = (const float*)d_in[5];
    float* out = (float*)d_out;
    const int B = in_sizes[0] / 4;

    const size_t smem = (size_t)(HID * HID + 4 * HID + 3 * HID +
                                 NWARP * (S * HID + S * 2 * HID)) * sizeof(float);
    cudaFuncSetAttribute(lnn_kernel,
                         cudaFuncAttributeMaxDynamicSharedMemorySize,
                         (int)smem);
    lnn_kernel<<<148, NTHR, smem>>>(X, W1, b1, W2, b2, W3, out, B);
}

// round 5
// speedup vs baseline: 2.1884x; 2.1884x over previous
#include <cuda_runtime.h>
#include <cuda_fp16.h>
#include <cstdint>

#define NTHR 512

// ---- shared memory byte offsets ----
#define BF_HI 0                 // W2^T [k][j] fp16 hi (GEMM1 B), 32KB
#define BF_LO (32*1024)
#define BB_HI (64*1024)         // W2   [j][k] fp16 hi (GEMM2 B)
#define BB_LO (96*1024)
#define A_HI  (128*1024)        // activations (H1 then G2) [row][col] fp16 hi
#define A_LO  (160*1024)
#define OW1   (192*1024)        // 4*128 floats
#define OB1   (OW1 + 2048)
#define OB2   (OB1 + 512)
#define OW3   (OB2 + 512)
#define OTRIG (OW3 + 512)       // 128 * 8 floats
#define OPF   (OTRIG + 128*8*4) // 4 * 128 * 4 floats
#define SMEM_TOTAL (OPF + 4*128*4*4)

__device__ __forceinline__ uint32_t smem_u32(const void* p) {
    uint32_t a;
    asm("{ .reg .u64 t; cvta.to.shared.u64 t, %1; cvt.u32.u64 %0, t; }"
        : "=r"(a) : "l"(p));
    return a;
}
__device__ __forceinline__ float ftanh(float x) {
    float e = __expf(2.0f * x);
    return 1.0f - __fdividef(2.0f, e + 1.0f);
}
// swizzled byte offset of 16B chunk (row r, chunk) in a 128x128 fp16 tile
__device__ __forceinline__ uint32_t swz(int r, int chunk) {
    return (uint32_t)((r << 8) + (((chunk ^ (r & 7)) & 15) << 4));
}
// swizzled byte offset of half element (r, c)
__device__ __forceinline__ uint32_t helem(int r, int c) {
    return swz(r, c >> 3) + ((c & 7) << 1);
}
__device__ __forceinline__ void split2(float x0, float x1,
                                       uint32_t& hi, uint32_t& lo) {
    const __half h0 = __float2half_rn(x0), h1 = __float2half_rn(x1);
    const __half l0 = __float2half_rn(x0 - __half2float(h0));
    const __half l1 = __float2half_rn(x1 - __half2float(h1));
    hi = (uint32_t)__half_as_ushort(h0) | ((uint32_t)__half_as_ushort(h1) << 16);
    lo = (uint32_t)__half_as_ushort(l0) | ((uint32_t)__half_as_ushort(l1) << 16);
}
__device__ __forceinline__ void ldsm4(uint32_t& r0, uint32_t& r1,
                                      uint32_t& r2, uint32_t& r3, uint32_t a) {
    asm volatile("ldmatrix.sync.aligned.m8n8.x4.shared.b16 {%0,%1,%2,%3}, [%4];"
                 : "=r"(r0), "=r"(r1), "=r"(r2), "=r"(r3) : "r"(a));
}
__device__ __forceinline__ void ldsm2(uint32_t& r0, uint32_t& r1, uint32_t a) {
    asm volatile("ldmatrix.sync.aligned.m8n8.x2.shared.b16 {%0,%1}, [%2];"
                 : "=r"(r0), "=r"(r1) : "r"(a));
}
__device__ __forceinline__ void mma16816(float d[4],
                                         uint32_t a0, uint32_t a1,
                                         uint32_t a2, uint32_t a3,
                                         uint32_t b0, uint32_t b1) {
    asm volatile(
        "mma.sync.aligned.m16n8k16.row.col.f32.f16.f16.f32 "
        "{%0,%1,%2,%3}, {%4,%5,%6,%7}, {%8,%9}, {%0,%1,%2,%3};"
        : "+f"(d[0]), "+f"(d[1]), "+f"(d[2]), "+f"(d[3])
        : "r"(a0), "r"(a1), "r"(a2), "r"(a3), "r"(b0), "r"(b1));
}

// D(128x128) = A(128x128) @ B-op, 3-term split-fp16. Warp computes m32 x n32.
__device__ __forceinline__ void gemm_tile(uint32_t sb, uint32_t Ah, uint32_t Al,
                                          uint32_t Bh, uint32_t Bl,
                                          int mbase, int nbase, int lane,
                                          float acc[2][4][4]) {
    #pragma unroll
    for (int mt = 0; mt < 2; mt++)
        #pragma unroll
        for (int nt = 0; nt < 4; nt++)
            #pragma unroll
            for (int e = 0; e < 4; e++) acc[mt][nt][e] = 0.0f;

    #pragma unroll
    for (int k = 0; k < 8; k++) {
        const int cb = k * 2;
        uint32_t aH[2][4], aL[2][4];
        #pragma unroll
        for (int mt = 0; mt < 2; mt++) {
            const int r = mbase + mt * 16 + (lane & 15);
            const uint32_t off = swz(r, cb + (lane >> 4));
            ldsm4(aH[mt][0], aH[mt][1], aH[mt][2], aH[mt][3], sb + Ah + off);
            ldsm4(aL[mt][0], aL[mt][1], aL[mt][2], aL[mt][3], sb + Al + off);
        }
        uint32_t bH[4][2], bL[4][2];
        #pragma unroll
        for (int nt = 0; nt < 4; nt++) {
            const int r = nbase + nt * 8 + (lane & 7);
            const uint32_t off = swz(r, cb + ((lane >> 3) & 1));
            ldsm2(bH[nt][0], bH[nt][1], sb + Bh + off);
            ldsm2(bL[nt][0], bL[nt][1], sb + Bl + off);
        }
        #pragma unroll
        for (int mt = 0; mt < 2; mt++)
            #pragma unroll
            for (int nt = 0; nt < 4; nt++) {
                mma16816(acc[mt][nt], aH[mt][0], aH[mt][1], aH[mt][2], aH[mt][3],
                         bH[nt][0], bH[nt][1]);
                mma16816(acc[mt][nt], aH[mt][0], aH[mt][1], aH[mt][2], aH[mt][3],
                         bL[nt][0], bL[nt][1]);
                mma16816(acc[mt][nt], aL[mt][0], aL[mt][1], aL[mt][2], aL[mt][3],
                         bH[nt][0], bH[nt][1]);
            }
    }
}

__global__ void __launch_bounds__(NTHR, 1)
lnn_kernel(const float* __restrict__ X,
           const float* __restrict__ W1, const float* __restrict__ b1,
           const float* __restrict__ W2, const float* __restrict__ b2,
           const float* __restrict__ W3,
           float* __restrict__ out, int B)
{
    extern __shared__ char smem[];
    const uint32_t sb = smem_u32(smem);
    const int tid  = threadIdx.x;
    const int wid  = tid >> 5;
    const int lane = tid & 31;

    // ---- stage W2 split-fp16, both layouts ----
    for (int idx = tid; idx < 128 * 128; idx += NTHR) {
        const int j = idx >> 7, k = idx & 127;
        const float v = W2[idx];
        const __half h = __float2half_rn(v);
        const __half l = __float2half_rn(v - __half2float(h));
        const uint16_t hu = __half_as_ushort(h), lu = __half_as_ushort(l);
        const uint32_t of = helem(k, j);     // fwd: rows=k, cols=j
        *(uint16_t*)(smem + BF_HI + of) = hu;
        *(uint16_t*)(smem + BF_LO + of) = lu;
        const uint32_t ob = helem(j, k);     // bwd: rows=j, cols=k
        *(uint16_t*)(smem + BB_HI + ob) = hu;
        *(uint16_t*)(smem + BB_LO + ob) = lu;
    }
    {
        float* w1s = (float*)(smem + OW1);
        for (int i = tid; i < 512; i += NTHR) w1s[i] = W1[i];
        float* d1 = (float*)(smem + OB1);
        float* d2 = (float*)(smem + OB2);
        float* d3 = (float*)(smem + OW3);
        for (int i = tid; i < 128; i += NTHR) {
            d1[i] = b1[i]; d2[i] = b2[i]; d3[i] = W3[i];
        }
    }
    __syncthreads();

    const float* w1p = (const float*)(smem + OW1);
    const float* b1p = (const float*)(smem + OB1);
    const float* b2p = (const float*)(smem + OB2);
    const float* w3p = (const float*)(smem + OW3);
    float* trig = (float*)(smem + OTRIG);
    float* pfb  = (float*)(smem + OPF);

    const int mg = wid >> 2, ng = wid & 3;
    const int mbase = mg * 32, nbase = ng * 32;

    const int nTiles = (B + 127) >> 7;
    for (int t = blockIdx.x; t < nTiles; t += gridDim.x) {
        // ---- 1. trig staging ----
        if (tid < 128) {
            const int g = (t << 7) + tid;
            if (g < B) {
                const float4 x = reinterpret_cast<const float4*>(X)[g];
                float s1, c1, s2, c2;
                __sincosf(x.x, &s1, &c1);
                __sincosf(x.y, &s2, &c2);
                float* tr = trig + tid * 8;
                tr[0] = s1; tr[1] = c1; tr[2] = s2; tr[3] = c2;
                tr[4] = x.z; tr[5] = x.w;
            }
        }
        __syncthreads();

        // ---- 2. layer 1: H1 = tanh(feat @ W1 + b1) -> A (split) ----
        {
            const int s = tid & 127;
            const int q = tid >> 7;           // 0..3, owns chunks q*4..q*4+3
            const float* tr = trig + s * 8;
            const float s1 = tr[0], c1 = tr[1], s2 = tr[2], c2 = tr[3];
            #pragma unroll
            for (int qq = 0; qq < 4; qq++) {
                const int cc = q * 4 + qq;
                uint32_t hw[4], lw[4];
                #pragma unroll
                for (int p = 0; p < 4; p++) {
                    const int j = cc * 8 + p * 2;
                    float z0 = b1p[j], z1 = b1p[j + 1];
                    z0 = fmaf(s1, w1p[j], z0);       z1 = fmaf(s1, w1p[j + 1], z1);
                    z0 = fmaf(c1, w1p[128 + j], z0); z1 = fmaf(c1, w1p[129 + j], z1);
                    z0 = fmaf(s2, w1p[256 + j], z0); z1 = fmaf(s2, w1p[257 + j], z1);
                    z0 = fmaf(c2, w1p[384 + j], z0); z1 = fmaf(c2, w1p[385 + j], z1);
                    split2(ftanh(z0), ftanh(z1), hw[p], lw[p]);
                }
                const uint32_t off = swz(s, cc);
                *(uint4*)(smem + A_HI + off) = make_uint4(hw[0], hw[1], hw[2], hw[3]);
                *(uint4*)(smem + A_LO + off) = make_uint4(lw[0], lw[1], lw[2], lw[3]);
            }
        }
        __syncthreads();

        // ---- 3. GEMM1: Z2 = H1 @ W2 ----
        float acc[2][4][4];
        gemm_tile(sb, A_HI, A_LO, BF_HI, BF_LO, mbase, nbase, lane, acc);
        __syncthreads();   // all reads of A done before epilogue overwrites it

        // ---- 4. epilogue 1: G2 = W3*(1-tanh(Z2+b2)^2) -> A (split) ----
        #pragma unroll
        for (int mt = 0; mt < 2; mt++)
            #pragma unroll
            for (int hf = 0; hf < 2; hf++) {
                const int row = mbase + mt * 16 + (lane >> 2) + hf * 8;
                #pragma unroll
                for (int nt = 0; nt < 4; nt++) {
                    const int c = nbase + nt * 8 + 2 * (lane & 3);
                    const float z0 = acc[mt][nt][hf * 2]     + b2p[c];
                    const float z1 = acc[mt][nt][hf * 2 + 1] + b2p[c + 1];
                    const float t0 = ftanh(z0), t1 = ftanh(z1);
                    const float g0 = w3p[c]     * (1.0f - t0 * t0);
                    const float g1 = w3p[c + 1] * (1.0f - t1 * t1);
                    uint32_t hi, lo;
                    split2(g0, g1, hi, lo);
                    const uint32_t off = helem(row, c);
                    *(uint32_t*)(smem + A_HI + off) = hi;
                    *(uint32_t*)(smem + A_LO + off) = lo;
                }
            }
        __syncthreads();

        // ---- 5. GEMM2: G1pre = G2 @ W2^T ----
        gemm_tile(sb, A_HI, A_LO, BB_HI, BB_LO, mbase, nbase, lane, acc);

        // ---- 6. epilogue 2: g1=(1-h1^2)*pre ; pf_i = sum_j W1[i][j]*g1[j] ----
        #pragma unroll
        for (int mt = 0; mt < 2; mt++)
            #pragma unroll
            for (int hf = 0; hf < 2; hf++) {
                const int row = mbase + mt * 16 + (lane >> 2) + hf * 8;
                const float* tr = trig + row * 8;
                const float s1 = tr[0], c1 = tr[1], s2 = tr[2], c2 = tr[3];
                float pf0 = 0.f, pf1 = 0.f, pf2 = 0.f, pf3 = 0.f;
                #pragma unroll
                for (int nt = 0; nt < 4; nt++) {
                    const int c = nbase + nt * 8 + 2 * (lane & 3);
                    #pragma unroll
                    for (int e = 0; e < 2; e++) {
                        const int j = c + e;
                        const float pre = acc[mt][nt][hf * 2 + e];
                        const float a0 = w1p[j],       a1 = w1p[128 + j];
                        const float a2 = w1p[256 + j], a3 = w1p[384 + j];
                        float z = b1p[j];
                        z = fmaf(s1, a0, z); z = fmaf(c1, a1, z);
                        z = fmaf(s2, a2, z); z = fmaf(c2, a3, z);
                        const float h = ftanh(z);
                        const float g1 = (1.0f - h * h) * pre;
                        pf0 = fmaf(a0, g1, pf0); pf1 = fmaf(a1, g1, pf1);
                        pf2 = fmaf(a2, g1, pf2); pf3 = fmaf(a3, g1, pf3);
                    }
                }
                pf0 += __shfl_xor_sync(0xffffffffu, pf0, 1);
                pf1 += __shfl_xor_sync(0xffffffffu, pf1, 1);
                pf2 += __shfl_xor_sync(0xffffffffu, pf2, 1);
                pf3 += __shfl_xor_sync(0xffffffffu, pf3, 1);
                pf0 += __shfl_xor_sync(0xffffffffu, pf0, 2);
                pf1 += __shfl_xor_sync(0xffffffffu, pf1, 2);
                pf2 += __shfl_xor_sync(0xffffffffu, pf2, 2);
                pf3 += __shfl_xor_sync(0xffffffffu, pf3, 2);
                if ((lane & 3) == 0)
                    *(float4*)(pfb + (ng * 128 + row) * 4) =
                        make_float4(pf0, pf1, pf2, pf3);
            }
        __syncthreads();

        // ---- 7. combine partials + analytic closure + 2x2 solve ----
        if (tid < 128) {
            const int gidx = (t << 7) + tid;
            if (gidx < B) {
                float p0 = 0.f, p1 = 0.f, p2 = 0.f, p3 = 0.f;
                #pragma unroll
                for (int q = 0; q < 4; q++) {
                    const float4 v = *(const float4*)(pfb + (q * 128 + tid) * 4);
                    p0 += v.x; p1 += v.y; p2 += v.z; p3 += v.w;
                }
                const float* tr = trig + tid * 8;
                const float s1 = tr[0], c1 = tr[1], s2 = tr[2], c2 = tr[3];
                const float w1v = tr[4], w2v = tr[5];
                const float sd = s1 * c2 - c1 * s2;
                const float cd = c1 * c2 + s1 * s2;
                const float dV1 = p0 * c1 - p1 * s1;
                const float dV2 = p2 * c2 - p3 * s2;
                const float dw = w2v - w1v;
                const float rhs1 = -w1v * w2v * sd - dV1 - w2v * sd * dw;
                const float rhs2 =  w1v * w2v * sd - dV2 - w1v * sd * dw;
                const float det = 2.0f - cd * cd;
                const float inv = __fdividef(1.0f, det);
                const float q1 = (rhs1 - cd * rhs2) * inv;
                const float q2 = (2.0f * rhs2 - cd * rhs1) * inv;
                reinterpret_cast<float4*>(out)[gidx] = make_float4(w1v, w2v, q1, q2);
            }
        }
        __syncthreads();
    }
}

extern "C" void kernel_launch(void* const* d_in, const int* in_sizes, int n_in,
                              void* d_out, int out_size)
{
    const float* X  = (const float*)d_in[0];
    const float* W1 = (const float*)d_in[1];
    const float* b1 = (const float*)d_in[2];
    const float* W2 = (const float*)d_in[3];
    const float* b2 = (const float*)d_in[4];
    const float* W3 = (const float*)d_in[5];
    float* out = (float*)d_out;
    const int B = in_sizes[0] / 4;

    cudaFuncSetAttribute(lnn_kernel,
                         cudaFuncAttributeMaxDynamicSharedMemorySize,
                         SMEM_TOTAL);
    lnn_kernel<<<148, NTHR, SMEM_TOTAL>>>(X, W1, b1, W2, b2, W3, out, B);
}

// round 8
// speedup vs baseline: 2.3788x; 1.0870x over previous
#include <cuda_runtime.h>
#include <cuda_fp16.h>
#include <cstdint>

#define NTHR 512

// ---- shared memory byte offsets ----
#define BB_HI 0                 // W2 [j][k] fp16 hi (both GEMMs), 32KB
#define BB_LO (32*1024)
#define H1_HI (64*1024)         // H1 tile [s][j] split-fp16
#define H1_LO (96*1024)
#define G2_HI (128*1024)        // G2 tile [s][k] split-fp16
#define G2_LO (160*1024)
#define OW1   (192*1024)        // 4*128 floats
#define OB1   (OW1 + 2048)
#define OB2   (OB1 + 512)
#define OW3   (OB2 + 512)
#define OTRIG (OW3 + 512)       // 128 * 8 floats
#define OPF   (OTRIG + 128*8*4) // 4 * 128 * 4 floats
#define SMEM_TOTAL (OPF + 4*128*4*4)

__device__ __forceinline__ uint32_t smem_u32(const void* p) {
    uint32_t a;
    asm("{ .reg .u64 t; cvta.to.shared.u64 t, %1; cvt.u32.u64 %0, t; }"
        : "=r"(a) : "l"(p));
    return a;
}
__device__ __forceinline__ float ftanh(float x) {
    float e = __expf(2.0f * x);
    return 1.0f - __fdividef(2.0f, e + 1.0f);
}
// swizzled byte offset of 16B chunk (row r, chunk) in a 128x128 fp16 tile
__device__ __forceinline__ uint32_t swz(int r, int chunk) {
    return (uint32_t)((r << 8) + (((chunk ^ (r & 7)) & 15) << 4));
}
__device__ __forceinline__ uint32_t helem(int r, int c) {
    return swz(r, c >> 3) + ((c & 7) << 1);
}
__device__ __forceinline__ void split2(float x0, float x1,
                                       uint32_t& hi, uint32_t& lo) {
    const __half h0 = __float2half_rn(x0), h1 = __float2half_rn(x1);
    const __half l0 = __float2half_rn(x0 - __half2float(h0));
    const __half l1 = __float2half_rn(x1 - __half2float(h1));
    hi = (uint32_t)__half_as_ushort(h0) | ((uint32_t)__half_as_ushort(h1) << 16);
    lo = (uint32_t)__half_as_ushort(l0) | ((uint32_t)__half_as_ushort(l1) << 16);
}
__device__ __forceinline__ void ldsm4(uint32_t& r0, uint32_t& r1,
                                      uint32_t& r2, uint32_t& r3, uint32_t a) {
    asm volatile("ldmatrix.sync.aligned.m8n8.x4.shared.b16 {%0,%1,%2,%3}, [%4];"
                 : "=r"(r0), "=r"(r1), "=r"(r2), "=r"(r3) : "r"(a));
}
__device__ __forceinline__ void ldsm2(uint32_t& r0, uint32_t& r1, uint32_t a) {
    asm volatile("ldmatrix.sync.aligned.m8n8.x2.shared.b16 {%0,%1}, [%2];"
                 : "=r"(r0), "=r"(r1) : "r"(a));
}
__device__ __forceinline__ void ldsm2t(uint32_t& r0, uint32_t& r1, uint32_t a) {
    asm volatile("ldmatrix.sync.aligned.m8n8.x2.trans.shared.b16 {%0,%1}, [%2];"
                 : "=r"(r0), "=r"(r1) : "r"(a));
}
__device__ __forceinline__ void mma16816(float d[4],
                                         uint32_t a0, uint32_t a1,
                                         uint32_t a2, uint32_t a3,
                                         uint32_t b0, uint32_t b1) {
    asm volatile(
        "mma.sync.aligned.m16n8k16.row.col.f32.f16.f16.f32 "
        "{%0,%1,%2,%3}, {%4,%5,%6,%7}, {%8,%9}, {%0,%1,%2,%3};"
        : "+f"(d[0]), "+f"(d[1]), "+f"(d[2]), "+f"(d[3])
        : "r"(a0), "r"(a1), "r"(a2), "r"(a3), "r"(b0), "r"(b1));
}

// D(128x128) = A @ op(B); 3-term split-fp16; warp computes m32 x n32.
// TRANSB=false: B memory [n][kdim] (non-trans ldmatrix)
// TRANSB=true : B memory [kdim][n] (trans ldmatrix)
template <bool TRANSB>
__device__ __forceinline__ void gemm_tile(uint32_t sb, uint32_t Ah, uint32_t Al,
                                          uint32_t Bh, uint32_t Bl,
                                          int mbase, int nbase, int lane,
                                          float acc[2][4][4]) {
    #pragma unroll
    for (int mt = 0; mt < 2; mt++)
        #pragma unroll
        for (int nt = 0; nt < 4; nt++)
            #pragma unroll
            for (int e = 0; e < 4; e++) acc[mt][nt][e] = 0.0f;

    #pragma unroll
    for (int k = 0; k < 8; k++) {
        const int cb = k * 2;
        uint32_t aH[2][4], aL[2][4];
        #pragma unroll
        for (int mt = 0; mt < 2; mt++) {
            const int r = mbase + mt * 16 + (lane & 15);
            const uint32_t off = swz(r, cb + (lane >> 4));
            ldsm4(aH[mt][0], aH[mt][1], aH[mt][2], aH[mt][3], sb + Ah + off);
            ldsm4(aL[mt][0], aL[mt][1], aL[mt][2], aL[mt][3], sb + Al + off);
        }
        uint32_t bH[4][2], bL[4][2];
        #pragma unroll
        for (int nt = 0; nt < 4; nt++) {
            if (TRANSB) {
                // rows = kdim (k*16 .. +15), 16B chunk at column nbase+nt*8
                const int r = k * 16 + (lane & 15);
                const uint32_t off = swz(r, (nbase + nt * 8) >> 3);
                ldsm2t(bH[nt][0], bH[nt][1], sb + Bh + off);
                ldsm2t(bL[nt][0], bL[nt][1], sb + Bl + off);
            } else {
                const int r = nbase + nt * 8 + (lane & 7);
                const uint32_t off = swz(r, cb + ((lane >> 3) & 1));
                ldsm2(bH[nt][0], bH[nt][1], sb + Bh + off);
                ldsm2(bL[nt][0], bL[nt][1], sb + Bl + off);
            }
        }
        #pragma unroll
        for (int mt = 0; mt < 2; mt++)
            #pragma unroll
            for (int nt = 0; nt < 4; nt++) {
                mma16816(acc[mt][nt], aH[mt][0], aH[mt][1], aH[mt][2], aH[mt][3],
                         bH[nt][0], bH[nt][1]);
                mma16816(acc[mt][nt], aH[mt][0], aH[mt][1], aH[mt][2], aH[mt][3],
                         bL[nt][0], bL[nt][1]);
                mma16816(acc[mt][nt], aL[mt][0], aL[mt][1], aL[mt][2], aL[mt][3],
                         bH[nt][0], bH[nt][1]);
            }
    }
}

__global__ void __launch_bounds__(NTHR, 1)
lnn_kernel(const float* __restrict__ X,
           const float* __restrict__ W1, const float* __restrict__ b1,
           const float* __restrict__ W2, const float* __restrict__ b2,
           const float* __restrict__ W3,
           float* __restrict__ out, int B)
{
    extern __shared__ char smem[];
    const uint32_t sb = smem_u32(smem);
    const int tid  = threadIdx.x;
    const int wid  = tid >> 5;
    const int lane = tid & 31;

    // ---- stage W2 split-fp16 (single [j][k] layout) ----
    for (int idx = tid; idx < 128 * 128; idx += NTHR) {
        const int j = idx >> 7, k = idx & 127;
        const float v = W2[idx];
        const __half h = __float2half_rn(v);
        const __half l = __float2half_rn(v - __half2float(h));
        const uint32_t ob = helem(j, k);
        *(uint16_t*)(smem + BB_HI + ob) = __half_as_ushort(h);
        *(uint16_t*)(smem + BB_LO + ob) = __half_as_ushort(l);
    }
    {
        float* w1s = (float*)(smem + OW1);
        for (int i = tid; i < 512; i += NTHR) w1s[i] = W1[i];
        float* d1 = (float*)(smem + OB1);
        float* d2 = (float*)(smem + OB2);
        float* d3 = (float*)(smem + OW3);
        for (int i = tid; i < 128; i += NTHR) {
            d1[i] = b1[i]; d2[i] = b2[i]; d3[i] = W3[i];
        }
    }
    __syncthreads();

    const float* w1p = (const float*)(smem + OW1);
    const float* b1p = (const float*)(smem + OB1);
    const float* b2p = (const float*)(smem + OB2);
    const float* w3p = (const float*)(smem + OW3);
    float* trig = (float*)(smem + OTRIG);
    float* pfb  = (float*)(smem + OPF);

    const int mg = wid >> 2, ng = wid & 3;
    const int mbase = mg * 32, nbase = ng * 32;

    const int nTiles = (B + 127) >> 7;
    for (int t = blockIdx.x; t < nTiles; t += gridDim.x) {
        // ---- 1. trig staging ----
        if (tid < 128) {
            const int g = (t << 7) + tid;
            if (g < B) {
                const float4 x = reinterpret_cast<const float4*>(X)[g];
                float s1, c1, s2, c2;
                __sincosf(x.x, &s1, &c1);
                __sincosf(x.y, &s2, &c2);
                float* tr = trig + tid * 8;
                tr[0] = s1; tr[1] = c1; tr[2] = s2; tr[3] = c2;
                tr[4] = x.z; tr[5] = x.w;
            }
        }
        __syncthreads();

        // ---- 2. layer 1: H1 = tanh(feat @ W1 + b1) -> H1 buf (split) ----
        {
            const int s = tid & 127;
            const int q = tid >> 7;
            const float* tr = trig + s * 8;
            const float s1 = tr[0], c1 = tr[1], s2 = tr[2], c2 = tr[3];
            #pragma unroll
            for (int qq = 0; qq < 4; qq++) {
                const int cc = q * 4 + qq;
                uint32_t hw[4], lw[4];
                #pragma unroll
                for (int p = 0; p < 4; p++) {
                    const int j = cc * 8 + p * 2;
                    float z0 = b1p[j], z1 = b1p[j + 1];
                    z0 = fmaf(s1, w1p[j], z0);       z1 = fmaf(s1, w1p[j + 1], z1);
                    z0 = fmaf(c1, w1p[128 + j], z0); z1 = fmaf(c1, w1p[129 + j], z1);
                    z0 = fmaf(s2, w1p[256 + j], z0); z1 = fmaf(s2, w1p[257 + j], z1);
                    z0 = fmaf(c2, w1p[384 + j], z0); z1 = fmaf(c2, w1p[385 + j], z1);
                    split2(ftanh(z0), ftanh(z1), hw[p], lw[p]);
                }
                const uint32_t off = swz(s, cc);
                *(uint4*)(smem + H1_HI + off) = make_uint4(hw[0], hw[1], hw[2], hw[3]);
                *(uint4*)(smem + H1_LO + off) = make_uint4(lw[0], lw[1], lw[2], lw[3]);
            }
        }
        __syncthreads();

        // ---- 3. GEMM1: Z2 = H1 @ W2 (B via trans ldmatrix on [j][k]) ----
        float acc[2][4][4];
        gemm_tile<true>(sb, H1_HI, H1_LO, BB_HI, BB_LO, mbase, nbase, lane, acc);

        // ---- 4. epilogue 1: G2 = W3*(1-tanh(Z2+b2)^2) -> G2 buf ----
        #pragma unroll
        for (int mt = 0; mt < 2; mt++)
            #pragma unroll
            for (int hf = 0; hf < 2; hf++) {
                const int row = mbase + mt * 16 + (lane >> 2) + hf * 8;
                #pragma unroll
                for (int nt = 0; nt < 4; nt++) {
                    const int c = nbase + nt * 8 + 2 * (lane & 3);
                    const float z0 = acc[mt][nt][hf * 2]     + b2p[c];
                    const float z1 = acc[mt][nt][hf * 2 + 1] + b2p[c + 1];
                    const float t0 = ftanh(z0), t1 = ftanh(z1);
                    const float g0 = w3p[c]     * (1.0f - t0 * t0);
                    const float g1 = w3p[c + 1] * (1.0f - t1 * t1);
                    uint32_t hi, lo;
                    split2(g0, g1, hi, lo);
                    const uint32_t off = helem(row, c);
                    *(uint32_t*)(smem + G2_HI + off) = hi;
                    *(uint32_t*)(smem + G2_LO + off) = lo;
                }
            }
        __syncthreads();

        // ---- 5. GEMM2: G1pre = G2 @ W2^T (B non-trans on [j][k]) ----
        gemm_tile<false>(sb, G2_HI, G2_LO, BB_HI, BB_LO, mbase, nbase, lane, acc);

        // ---- 6. epilogue 2: read h1 from H1 buf; pf_i = sum_j W1[i][j]*g1[j] ----
        #pragma unroll
        for (int mt = 0; mt < 2; mt++)
            #pragma unroll
            for (int hf = 0; hf < 2; hf++) {
                const int row = mbase + mt * 16 + (lane >> 2) + hf * 8;
                float pf0 = 0.f, pf1 = 0.f, pf2 = 0.f, pf3 = 0.f;
                #pragma unroll
                for (int nt = 0; nt < 4; nt++) {
                    const int c = nbase + nt * 8 + 2 * (lane & 3);
                    const uint32_t off = helem(row, c);
                    const __half2 hh = *(const __half2*)(smem + H1_HI + off);
                    const __half2 hl = *(const __half2*)(smem + H1_LO + off);
                    const float2 fh = __half22float2(hh);
                    const float2 fl = __half22float2(hl);
                    const float hv[2] = {fh.x + fl.x, fh.y + fl.y};
                    #pragma unroll
                    for (int e = 0; e < 2; e++) {
                        const int j = c + e;
                        const float pre = acc[mt][nt][hf * 2 + e];
                        const float h = hv[e];
                        const float g1 = (1.0f - h * h) * pre;
                        const float a0 = w1p[j],       a1 = w1p[128 + j];
                        const float a2 = w1p[256 + j], a3 = w1p[384 + j];
                        pf0 = fmaf(a0, g1, pf0); pf1 = fmaf(a1, g1, pf1);
                        pf2 = fmaf(a2, g1, pf2); pf3 = fmaf(a3, g1, pf3);
                    }
                }
                pf0 += __shfl_xor_sync(0xffffffffu, pf0, 1);
                pf1 += __shfl_xor_sync(0xffffffffu, pf1, 1);
                pf2 += __shfl_xor_sync(0xffffffffu, pf2, 1);
                pf3 += __shfl_xor_sync(0xffffffffu, pf3, 1);
                pf0 += __shfl_xor_sync(0xffffffffu, pf0, 2);
                pf1 += __shfl_xor_sync(0xffffffffu, pf1, 2);
                pf2 += __shfl_xor_sync(0xffffffffu, pf2, 2);
                pf3 += __shfl_xor_sync(0xffffffffu, pf3, 2);
                if ((lane & 3) == 0)
                    *(float4*)(pfb + (ng * 128 + row) * 4) =
                        make_float4(pf0, pf1, pf2, pf3);
            }
        __syncthreads();

        // ---- 7. combine partials + analytic closure + 2x2 solve ----
        if (tid < 128) {
            const int gidx = (t << 7) + tid;
            if (gidx < B) {
                float p0 = 0.f, p1 = 0.f, p2 = 0.f, p3 = 0.f;
                #pragma unroll
                for (int q = 0; q < 4; q++) {
                    const float4 v = *(const float4*)(pfb + (q * 128 + tid) * 4);
                    p0 += v.x; p1 += v.y; p2 += v.z; p3 += v.w;
                }
                const float* tr = trig + tid * 8;
                const float s1 = tr[0], c1 = tr[1], s2 = tr[2], c2 = tr[3];
                const float w1v = tr[4], w2v = tr[5];
                const float sd = s1 * c2 - c1 * s2;
                const float cd = c1 * c2 + s1 * s2;
                const float dV1 = p0 * c1 - p1 * s1;
                const float dV2 = p2 * c2 - p3 * s2;
                const float dw = w2v - w1v;
                const float rhs1 = -w1v * w2v * sd - dV1 - w2v * sd * dw;
                const float rhs2 =  w1v * w2v * sd - dV2 - w1v * sd * dw;
                const float det = 2.0f - cd * cd;
                const float inv = __fdividef(1.0f, det);
                const float q1 = (rhs1 - cd * rhs2) * inv;
                const float q2 = (2.0f * rhs2 - cd * rhs1) * inv;
                reinterpret_cast<float4*>(out)[gidx] = make_float4(w1v, w2v, q1, q2);
            }
        }
        __syncthreads();
    }
}

extern "C" void kernel_launch(void* const* d_in, const int* in_sizes, int n_in,
                              void* d_out, int out_size)
{
    const float* X  = (const float*)d_in[0];
    const float* W1 = (const float*)d_in[1];
    const float* b1 = (const float*)d_in[2];
    const float* W2 = (const float*)d_in[3];
    const float* b2 = (const float*)d_in[4];
    const float* W3 = (const float*)d_in[5];
    float* out = (float*)d_out;
    const int B = in_sizes[0] / 4;

    cudaFuncSetAttribute(lnn_kernel,
                         cudaFuncAttributeMaxDynamicSharedMemorySize,
                         SMEM_TOTAL);
    lnn_kernel<<<148, NTHR, SMEM_TOTAL>>>(X, W1, b1, W2, b2, W3, out, B);
}

// round 9
// speedup vs baseline: 3.2821x; 1.3797x over previous
#include <cuda_runtime.h>
#include <cuda_fp16.h>
#include <cstdint>

#define NTHR 512

// ---- shared memory byte offsets ----
#define BB_HI 0                 // W2 [j][k] fp16 hi (both GEMMs), 32KB
#define BB_LO (32*1024)         // W2 [j][k] fp16 residual lo, 32KB
#define H1_OF (64*1024)         // H1 tile [s][j] fp16, 32KB
#define G2_OF (96*1024)         // G2 tile [s][k] fp16, 32KB
#define OW1   (128*1024)        // 4*128 floats
#define OB1   (OW1 + 2048)
#define OB2   (OB1 + 512)
#define OW3   (OB2 + 512)
#define OTRIG (OW3 + 512)       // 128 * 8 floats
#define OPF   (OTRIG + 128*8*4) // 4 * 128 * 4 floats
#define SMEM_TOTAL (OPF + 4*128*4*4)

__device__ __forceinline__ uint32_t smem_u32(const void* p) {
    uint32_t a;
    asm("{ .reg .u64 t; cvta.to.shared.u64 t, %1; cvt.u32.u64 %0, t; }"
        : "=r"(a) : "l"(p));
    return a;
}
__device__ __forceinline__ float ftanh(float x) {
    float e = __expf(2.0f * x);
    return 1.0f - __fdividef(2.0f, e + 1.0f);
}
// swizzled byte offset of 16B chunk (row r, chunk) in a 128x128 fp16 tile
__device__ __forceinline__ uint32_t swz(int r, int chunk) {
    return (uint32_t)((r << 8) + (((chunk ^ (r & 7)) & 15) << 4));
}
__device__ __forceinline__ uint32_t helem(int r, int c) {
    return swz(r, c >> 3) + ((c & 7) << 1);
}
__device__ __forceinline__ uint32_t packh2(float x0, float x1) {
    const __half2 h = __floats2half2_rn(x0, x1);
    return *(const uint32_t*)&h;
}
__device__ __forceinline__ void ldsm4(uint32_t& r0, uint32_t& r1,
                                      uint32_t& r2, uint32_t& r3, uint32_t a) {
    asm volatile("ldmatrix.sync.aligned.m8n8.x4.shared.b16 {%0,%1,%2,%3}, [%4];"
                 : "=r"(r0), "=r"(r1), "=r"(r2), "=r"(r3) : "r"(a));
}
__device__ __forceinline__ void ldsm4t(uint32_t& r0, uint32_t& r1,
                                       uint32_t& r2, uint32_t& r3, uint32_t a) {
    asm volatile("ldmatrix.sync.aligned.m8n8.x4.trans.shared.b16 {%0,%1,%2,%3}, [%4];"
                 : "=r"(r0), "=r"(r1), "=r"(r2), "=r"(r3) : "r"(a));
}
__device__ __forceinline__ void mma16816(float d[4],
                                         uint32_t a0, uint32_t a1,
                                         uint32_t a2, uint32_t a3,
                                         uint32_t b0, uint32_t b1) {
    asm volatile(
        "mma.sync.aligned.m16n8k16.row.col.f32.f16.f16.f32 "
        "{%0,%1,%2,%3}, {%4,%5,%6,%7}, {%8,%9}, {%0,%1,%2,%3};"
        : "+f"(d[0]), "+f"(d[1]), "+f"(d[2]), "+f"(d[3])
        : "r"(a0), "r"(a1), "r"(a2), "r"(a3), "r"(b0), "r"(b1));
}

// D(128x128) = A @ op(B); A plain fp16, B split hi+lo (2-term).
// Warp computes m32 x n32. TRANSB: B memory [kdim][n]; else [n][kdim].
template <bool TRANSB>
__device__ __forceinline__ void gemm_tile(uint32_t sb, uint32_t Aoff,
                                          uint32_t Bh, uint32_t Bl,
                                          int mbase, int nbase, int lane,
                                          float acc[2][4][4]) {
    #pragma unroll
    for (int mt = 0; mt < 2; mt++)
        #pragma unroll
        for (int nt = 0; nt < 4; nt++)
            #pragma unroll
            for (int e = 0; e < 4; e++) acc[mt][nt][e] = 0.0f;

    #pragma unroll
    for (int k = 0; k < 8; k++) {
        const int cb = k * 2;
        uint32_t aH[2][4];
        #pragma unroll
        for (int mt = 0; mt < 2; mt++) {
            const int r = mbase + mt * 16 + (lane & 15);
            const uint32_t off = swz(r, cb + (lane >> 4));
            ldsm4(aH[mt][0], aH[mt][1], aH[mt][2], aH[mt][3], sb + Aoff + off);
        }
        uint32_t bH[4][2], bL[4][2];
        #pragma unroll
        for (int p = 0; p < 2; p++) {
            const int ntl   = 2 * p + ((lane >> 4) & 1);
            const int khalf = (lane >> 3) & 1;
            uint32_t off;
            if (TRANSB) {
                const int r = k * 16 + khalf * 8 + (lane & 7);
                off = swz(r, (nbase + ntl * 8) >> 3);
                ldsm4t(bH[2*p][0], bH[2*p][1], bH[2*p+1][0], bH[2*p+1][1],
                       sb + Bh + off);
                ldsm4t(bL[2*p][0], bL[2*p][1], bL[2*p+1][0], bL[2*p+1][1],
                       sb + Bl + off);
            } else {
                const int r = nbase + ntl * 8 + (lane & 7);
                off = swz(r, cb + khalf);
                ldsm4(bH[2*p][0], bH[2*p][1], bH[2*p+1][0], bH[2*p+1][1],
                      sb + Bh + off);
                ldsm4(bL[2*p][0], bL[2*p][1], bL[2*p+1][0], bL[2*p+1][1],
                      sb + Bl + off);
            }
        }
        #pragma unroll
        for (int mt = 0; mt < 2; mt++)
            #pragma unroll
            for (int nt = 0; nt < 4; nt++) {
                mma16816(acc[mt][nt], aH[mt][0], aH[mt][1], aH[mt][2], aH[mt][3],
                         bH[nt][0], bH[nt][1]);
                mma16816(acc[mt][nt], aH[mt][0], aH[mt][1], aH[mt][2], aH[mt][3],
                         bL[nt][0], bL[nt][1]);
            }
    }
}

__global__ void __launch_bounds__(NTHR, 1)
lnn_kernel(const float* __restrict__ X,
           const float* __restrict__ W1, const float* __restrict__ b1,
           const float* __restrict__ W2, const float* __restrict__ b2,
           const float* __restrict__ W3,
           float* __restrict__ out, int B)
{
    extern __shared__ char smem[];
    const uint32_t sb = smem_u32(smem);
    const int tid  = threadIdx.x;
    const int wid  = tid >> 5;
    const int lane = tid & 31;

    // ---- stage W2 split-fp16 (single [j][k] layout) ----
    for (int idx = tid; idx < 128 * 128; idx += NTHR) {
        const int j = idx >> 7, k = idx & 127;
        const float v = W2[idx];
        const __half h = __float2half_rn(v);
        const __half l = __float2half_rn(v - __half2float(h));
        const uint32_t ob = helem(j, k);
        *(uint16_t*)(smem + BB_HI + ob) = __half_as_ushort(h);
        *(uint16_t*)(smem + BB_LO + ob) = __half_as_ushort(l);
    }
    {
        float* w1s = (float*)(smem + OW1);
        for (int i = tid; i < 512; i += NTHR) w1s[i] = W1[i];
        float* d1 = (float*)(smem + OB1);
        float* d2 = (float*)(smem + OB2);
        float* d3 = (float*)(smem + OW3);
        for (int i = tid; i < 128; i += NTHR) {
            d1[i] = b1[i]; d2[i] = b2[i]; d3[i] = W3[i];
        }
    }
    __syncthreads();

    const float* w1p = (const float*)(smem + OW1);
    const float* b1p = (const float*)(smem + OB1);
    const float* b2p = (const float*)(smem + OB2);
    const float* w3p = (const float*)(smem + OW3);
    float* trig = (float*)(smem + OTRIG);
    float* pfb  = (float*)(smem + OPF);

    const int mg = wid >> 2, ng = wid & 3;
    const int mbase = mg * 32, nbase = ng * 32;

    const int nTiles = (B + 127) >> 7;
    for (int t = blockIdx.x; t < nTiles; t += gridDim.x) {
        // ---- 1. trig staging ----
        if (tid < 128) {
            const int g = (t << 7) + tid;
            if (g < B) {
                const float4 x = reinterpret_cast<const float4*>(X)[g];
                float s1, c1, s2, c2;
                __sincosf(x.x, &s1, &c1);
                __sincosf(x.y, &s2, &c2);
                float* tr = trig + tid * 8;
                tr[0] = s1; tr[1] = c1; tr[2] = s2; tr[3] = c2;
                tr[4] = x.z; tr[5] = x.w;
            }
        }
        __syncthreads();

        // ---- 2. layer 1: H1 = tanh(feat @ W1 + b1) -> H1 buf (fp16) ----
        {
            const int s = tid & 127;
            const int q = tid >> 7;
            const float* tr = trig + s * 8;
            const float s1 = tr[0], c1 = tr[1], s2 = tr[2], c2 = tr[3];
            #pragma unroll
            for (int qq = 0; qq < 4; qq++) {
                const int cc = q * 4 + qq;
                uint32_t hw[4];
                #pragma unroll
                for (int p = 0; p < 4; p++) {
                    const int j = cc * 8 + p * 2;
                    float z0 = b1p[j], z1 = b1p[j + 1];
                    z0 = fmaf(s1, w1p[j], z0);       z1 = fmaf(s1, w1p[j + 1], z1);
                    z0 = fmaf(c1, w1p[128 + j], z0); z1 = fmaf(c1, w1p[129 + j], z1);
                    z0 = fmaf(s2, w1p[256 + j], z0); z1 = fmaf(s2, w1p[257 + j], z1);
                    z0 = fmaf(c2, w1p[384 + j], z0); z1 = fmaf(c2, w1p[385 + j], z1);
                    hw[p] = packh2(ftanh(z0), ftanh(z1));
                }
                const uint32_t off = swz(s, cc);
                *(uint4*)(smem + H1_OF + off) = make_uint4(hw[0], hw[1], hw[2], hw[3]);
            }
        }
        __syncthreads();

        // ---- 3. GEMM1: Z2 = H1 @ W2 (B via trans ldmatrix on [j][k]) ----
        float acc[2][4][4];
        gemm_tile<true>(sb, H1_OF, BB_HI, BB_LO, mbase, nbase, lane, acc);

        // ---- 4. epilogue 1: G2 = W3*(1-tanh(Z2+b2)^2) -> G2 buf (fp16) ----
        #pragma unroll
        for (int mt = 0; mt < 2; mt++)
            #pragma unroll
            for (int hf = 0; hf < 2; hf++) {
                const int row = mbase + mt * 16 + (lane >> 2) + hf * 8;
                #pragma unroll
                for (int nt = 0; nt < 4; nt++) {
                    const int c = nbase + nt * 8 + 2 * (lane & 3);
                    const float z0 = acc[mt][nt][hf * 2]     + b2p[c];
                    const float z1 = acc[mt][nt][hf * 2 + 1] + b2p[c + 1];
                    const float t0 = ftanh(z0), t1 = ftanh(z1);
                    const float g0 = w3p[c]     * (1.0f - t0 * t0);
                    const float g1 = w3p[c + 1] * (1.0f - t1 * t1);
                    *(uint32_t*)(smem + G2_OF + helem(row, c)) = packh2(g0, g1);
                }
            }
        __syncthreads();

        // ---- 5. GEMM2: G1pre = G2 @ W2^T (B non-trans on [j][k]) ----
        gemm_tile<false>(sb, G2_OF, BB_HI, BB_LO, mbase, nbase, lane, acc);

        // ---- 6. epilogue 2: h1 from H1 buf; pf_i = sum_j W1[i][j]*g1[j] ----
        #pragma unroll
        for (int mt = 0; mt < 2; mt++)
            #pragma unroll
            for (int hf = 0; hf < 2; hf++) {
                const int row = mbase + mt * 16 + (lane >> 2) + hf * 8;
                float pf0 = 0.f, pf1 = 0.f, pf2 = 0.f, pf3 = 0.f;
                #pragma unroll
                for (int nt = 0; nt < 4; nt++) {
                    const int c = nbase + nt * 8 + 2 * (lane & 3);
                    const __half2 hh = *(const __half2*)(smem + H1_OF + helem(row, c));
                    const float2 fh = __half22float2(hh);
                    const float hv[2] = {fh.x, fh.y};
                    #pragma unroll
                    for (int e = 0; e < 2; e++) {
                        const int j = c + e;
                        const float pre = acc[mt][nt][hf * 2 + e];
                        const float h = hv[e];
                        const float g1 = (1.0f - h * h) * pre;
                        const float a0 = w1p[j],       a1 = w1p[128 + j];
                        const float a2 = w1p[256 + j], a3 = w1p[384 + j];
                        pf0 = fmaf(a0, g1, pf0); pf1 = fmaf(a1, g1, pf1);
                        pf2 = fmaf(a2, g1, pf2); pf3 = fmaf(a3, g1, pf3);
                    }
                }
                pf0 += __shfl_xor_sync(0xffffffffu, pf0, 1);
                pf1 += __shfl_xor_sync(0xffffffffu, pf1, 1);
                pf2 += __shfl_xor_sync(0xffffffffu, pf2, 1);
                pf3 += __shfl_xor_sync(0xffffffffu, pf3, 1);
                pf0 += __shfl_xor_sync(0xffffffffu, pf0, 2);
                pf1 += __shfl_xor_sync(0xffffffffu, pf1, 2);
                pf2 += __shfl_xor_sync(0xffffffffu, pf2, 2);
                pf3 += __shfl_xor_sync(0xffffffffu, pf3, 2);
                if ((lane & 3) == 0)
                    *(float4*)(pfb + (ng * 128 + row) * 4) =
                        make_float4(pf0, pf1, pf2, pf3);
            }
        __syncthreads();

        // ---- 7. combine partials + analytic closure + 2x2 solve ----
        if (tid < 128) {
            const int gidx = (t << 7) + tid;
            if (gidx < B) {
                float p0 = 0.f, p1 = 0.f, p2 = 0.f, p3 = 0.f;
                #pragma unroll
                for (int q = 0; q < 4; q++) {
                    const float4 v = *(const float4*)(pfb + (q * 128 + tid) * 4);
                    p0 += v.x; p1 += v.y; p2 += v.z; p3 += v.w;
                }
                const float* tr = trig + tid * 8;
                const float s1 = tr[0], c1 = tr[1], s2 = tr[2], c2 = tr[3];
                const float w1v = tr[4], w2v = tr[5];
                const float sd = s1 * c2 - c1 * s2;
                const float cd = c1 * c2 + s1 * s2;
                const float dV1 = p0 * c1 - p1 * s1;
                const float dV2 = p2 * c2 - p3 * s2;
                const float dw = w2v - w1v;
                const float rhs1 = -w1v * w2v * sd - dV1 - w2v * sd * dw;
                const float rhs2 =  w1v * w2v * sd - dV2 - w1v * sd * dw;
                const float det = 2.0f - cd * cd;
                const float inv = __fdividef(1.0f, det);
                const float q1 = (rhs1 - cd * rhs2) * inv;
                const float q2 = (2.0f * rhs2 - cd * rhs1) * inv;
                reinterpret_cast<float4*>(out)[gidx] = make_float4(w1v, w2v, q1, q2);
            }
        }
        __syncthreads();
    }
}

extern "C" void kernel_launch(void* const* d_in, const int* in_sizes, int n_in,
                              void* d_out, int out_size)
{
    const float* X  = (const float*)d_in[0];
    const float* W1 = (const float*)d_in[1];
    const float* b1 = (const float*)d_in[2];
    const float* W2 = (const float*)d_in[3];
    const float* b2 = (const float*)d_in[4];
    const float* W3 = (const float*)d_in[5];
    float* out = (float*)d_out;
    const int B = in_sizes[0] / 4;

    cudaFuncSetAttribute(lnn_kernel,
                         cudaFuncAttributeMaxDynamicSharedMemorySize,
                         SMEM_TOTAL);
    lnn_kernel<<<148, NTHR, SMEM_TOTAL>>>(X, W1, b1, W2, b2, W3, out, B);
}

// round 10
// speedup vs baseline: 3.3984x; 1.0354x over previous
#include <cuda_runtime.h>
#include <cuda_fp16.h>
#include <cstdint>

#define NTHR 256

// ---- shared memory byte offsets ----
#define BB_HI 0                 // W2 [j][k] fp16 hi (both GEMMs), 32KB
#define BB_LO (32*1024)         // W2 [j][k] fp16 residual lo, 32KB
#define H1_OF (64*1024)         // H1 tile [s][j] fp16, 64 rows, 16KB
#define G2_OF (80*1024)         // G2 tile [s][k] fp16, 64 rows, 16KB
#define OW1   (96*1024)         // 4*128 floats
#define OB1   (OW1 + 2048)
#define OB2   (OB1 + 512)
#define OW3   (OB2 + 512)
#define OTRIG (OW3 + 512)       // 64 * 8 floats = 2KB
#define OPF   (OTRIG + 64*8*4)  // 4 * 64 * 4 floats = 4KB
#define SMEM_TOTAL (OPF + 4*64*4*4)

__device__ __forceinline__ uint32_t smem_u32(const void* p) {
    uint32_t a;
    asm("{ .reg .u64 t; cvta.to.shared.u64 t, %1; cvt.u32.u64 %0, t; }"
        : "=r"(a) : "l"(p));
    return a;
}
__device__ __forceinline__ float ftanh(float x) {
    float e = __expf(2.0f * x);
    return 1.0f - __fdividef(2.0f, e + 1.0f);
}
// swizzled byte offset of 16B chunk (row r, chunk) in a [rows]x128 fp16 tile
__device__ __forceinline__ uint32_t swz(int r, int chunk) {
    return (uint32_t)((r << 8) + (((chunk ^ (r & 7)) & 15) << 4));
}
__device__ __forceinline__ uint32_t helem(int r, int c) {
    return swz(r, c >> 3) + ((c & 7) << 1);
}
__device__ __forceinline__ uint32_t packh2(float x0, float x1) {
    const __half2 h = __floats2half2_rn(x0, x1);
    return *(const uint32_t*)&h;
}
__device__ __forceinline__ void ldsm4(uint32_t& r0, uint32_t& r1,
                                      uint32_t& r2, uint32_t& r3, uint32_t a) {
    asm volatile("ldmatrix.sync.aligned.m8n8.x4.shared.b16 {%0,%1,%2,%3}, [%4];"
                 : "=r"(r0), "=r"(r1), "=r"(r2), "=r"(r3) : "r"(a));
}
__device__ __forceinline__ void ldsm4t(uint32_t& r0, uint32_t& r1,
                                       uint32_t& r2, uint32_t& r3, uint32_t a) {
    asm volatile("ldmatrix.sync.aligned.m8n8.x4.trans.shared.b16 {%0,%1,%2,%3}, [%4];"
                 : "=r"(r0), "=r"(r1), "=r"(r2), "=r"(r3) : "r"(a));
}
__device__ __forceinline__ void mma16816(float d[4],
                                         uint32_t a0, uint32_t a1,
                                         uint32_t a2, uint32_t a3,
                                         uint32_t b0, uint32_t b1) {
    asm volatile(
        "mma.sync.aligned.m16n8k16.row.col.f32.f16.f16.f32 "
        "{%0,%1,%2,%3}, {%4,%5,%6,%7}, {%8,%9}, {%0,%1,%2,%3};"
        : "+f"(d[0]), "+f"(d[1]), "+f"(d[2]), "+f"(d[3])
        : "r"(a0), "r"(a1), "r"(a2), "r"(a3), "r"(b0), "r"(b1));
}

// D(64x128) = A(64x128) @ op(B); A plain fp16, B split hi+lo (2-term).
// 8 warps: warp computes m32 x n32. TRANSB: B memory [kdim][n]; else [n][kdim].
template <bool TRANSB>
__device__ __forceinline__ void gemm_tile(uint32_t sb, uint32_t Aoff,
                                          uint32_t Bh, uint32_t Bl,
                                          int mbase, int nbase, int lane,
                                          float acc[2][4][4]) {
    #pragma unroll
    for (int mt = 0; mt < 2; mt++)
        #pragma unroll
        for (int nt = 0; nt < 4; nt++)
            #pragma unroll
            for (int e = 0; e < 4; e++) acc[mt][nt][e] = 0.0f;

    #pragma unroll
    for (int k = 0; k < 8; k++) {
        const int cb = k * 2;
        uint32_t aH[2][4];
        #pragma unroll
        for (int mt = 0; mt < 2; mt++) {
            const int r = mbase + mt * 16 + (lane & 15);
            const uint32_t off = swz(r, cb + (lane >> 4));
            ldsm4(aH[mt][0], aH[mt][1], aH[mt][2], aH[mt][3], sb + Aoff + off);
        }
        uint32_t bH[4][2], bL[4][2];
        #pragma unroll
        for (int p = 0; p < 2; p++) {
            const int ntl   = 2 * p + ((lane >> 4) & 1);
            const int khalf = (lane >> 3) & 1;
            uint32_t off;
            if (TRANSB) {
                const int r = k * 16 + khalf * 8 + (lane & 7);
                off = swz(r, (nbase + ntl * 8) >> 3);
                ldsm4t(bH[2*p][0], bH[2*p][1], bH[2*p+1][0], bH[2*p+1][1],
                       sb + Bh + off);
                ldsm4t(bL[2*p][0], bL[2*p][1], bL[2*p+1][0], bL[2*p+1][1],
                       sb + Bl + off);
            } else {
                const int r = nbase + ntl * 8 + (lane & 7);
                off = swz(r, cb + khalf);
                ldsm4(bH[2*p][0], bH[2*p][1], bH[2*p+1][0], bH[2*p+1][1],
                      sb + Bh + off);
                ldsm4(bL[2*p][0], bL[2*p][1], bL[2*p+1][0], bL[2*p+1][1],
                      sb + Bl + off);
            }
        }
        #pragma unroll
        for (int mt = 0; mt < 2; mt++)
            #pragma unroll
            for (int nt = 0; nt < 4; nt++) {
                mma16816(acc[mt][nt], aH[mt][0], aH[mt][1], aH[mt][2], aH[mt][3],
                         bH[nt][0], bH[nt][1]);
                mma16816(acc[mt][nt], aH[mt][0], aH[mt][1], aH[mt][2], aH[mt][3],
                         bL[nt][0], bL[nt][1]);
            }
    }
}

__global__ void __launch_bounds__(NTHR, 2)
lnn_kernel(const float* __restrict__ X,
           const float* __restrict__ W1, const float* __restrict__ b1,
           const float* __restrict__ W2, const float* __restrict__ b2,
           const float* __restrict__ W3,
           float* __restrict__ out, int B)
{
    extern __shared__ char smem[];
    const uint32_t sb = smem_u32(smem);
    const int tid  = threadIdx.x;
    const int wid  = tid >> 5;
    const int lane = tid & 31;

    // ---- stage W2 split-fp16 (single [j][k] layout) ----
    for (int idx = tid; idx < 128 * 128; idx += NTHR) {
        const int j = idx >> 7, k = idx & 127;
        const float v = W2[idx];
        const __half h = __float2half_rn(v);
        const __half l = __float2half_rn(v - __half2float(h));
        const uint32_t ob = helem(j, k);
        *(uint16_t*)(smem + BB_HI + ob) = __half_as_ushort(h);
        *(uint16_t*)(smem + BB_LO + ob) = __half_as_ushort(l);
    }
    {
        float* w1s = (float*)(smem + OW1);
        for (int i = tid; i < 512; i += NTHR) w1s[i] = W1[i];
        float* d1 = (float*)(smem + OB1);
        float* d2 = (float*)(smem + OB2);
        float* d3 = (float*)(smem + OW3);
        for (int i = tid; i < 128; i += NTHR) {
            d1[i] = b1[i]; d2[i] = b2[i]; d3[i] = W3[i];
        }
    }
    __syncthreads();

    const float* w1p = (const float*)(smem + OW1);
    const float* b1p = (const float*)(smem + OB1);
    const float* b2p = (const float*)(smem + OB2);
    const float* w3p = (const float*)(smem + OW3);
    float* trig = (float*)(smem + OTRIG);
    float* pfb  = (float*)(smem + OPF);

    const int mg = wid >> 2, ng = wid & 3;     // 2 x 4 warp grid
    const int mbase = mg * 32, nbase = ng * 32;

    const int nTiles = (B + 63) >> 6;          // 64-sample tiles
    for (int t = blockIdx.x; t < nTiles; t += gridDim.x) {
        // ---- 1. trig staging ----
        if (tid < 64) {
            const int g = (t << 6) + tid;
            if (g < B) {
                const float4 x = reinterpret_cast<const float4*>(X)[g];
                float s1, c1, s2, c2;
                __sincosf(x.x, &s1, &c1);
                __sincosf(x.y, &s2, &c2);
                float* tr = trig + tid * 8;
                tr[0] = s1; tr[1] = c1; tr[2] = s2; tr[3] = c2;
                tr[4] = x.z; tr[5] = x.w;
            }
        }
        __syncthreads();

        // ---- 2. layer 1: H1 = tanh(feat @ W1 + b1) -> H1 buf (fp16) ----
        {
            const int s = tid & 63;
            const int q = tid >> 6;            // 0..3, owns chunks q*4..q*4+3
            const float* tr = trig + s * 8;
            const float s1 = tr[0], c1 = tr[1], s2 = tr[2], c2 = tr[3];
            #pragma unroll
            for (int qq = 0; qq < 4; qq++) {
                const int cc = q * 4 + qq;
                uint32_t hw[4];
                #pragma unroll
                for (int p = 0; p < 4; p++) {
                    const int j = cc * 8 + p * 2;
                    float z0 = b1p[j], z1 = b1p[j + 1];
                    z0 = fmaf(s1, w1p[j], z0);       z1 = fmaf(s1, w1p[j + 1], z1);
                    z0 = fmaf(c1, w1p[128 + j], z0); z1 = fmaf(c1, w1p[129 + j], z1);
                    z0 = fmaf(s2, w1p[256 + j], z0); z1 = fmaf(s2, w1p[257 + j], z1);
                    z0 = fmaf(c2, w1p[384 + j], z0); z1 = fmaf(c2, w1p[385 + j], z1);
                    hw[p] = packh2(ftanh(z0), ftanh(z1));
                }
                const uint32_t off = swz(s, cc);
                *(uint4*)(smem + H1_OF + off) = make_uint4(hw[0], hw[1], hw[2], hw[3]);
            }
        }
        __syncthreads();

        // ---- 3. GEMM1: Z2 = H1 @ W2 (B via trans ldmatrix on [j][k]) ----
        float acc[2][4][4];
        gemm_tile<true>(sb, H1_OF, BB_HI, BB_LO, mbase, nbase, lane, acc);

        // ---- 4. epilogue 1: G2 = W3*(1-tanh(Z2+b2)^2) -> G2 buf (fp16) ----
        #pragma unroll
        for (int mt = 0; mt < 2; mt++)
            #pragma unroll
            for (int hf = 0; hf < 2; hf++) {
                const int row = mbase + mt * 16 + (lane >> 2) + hf * 8;
                #pragma unroll
                for (int nt = 0; nt < 4; nt++) {
                    const int c = nbase + nt * 8 + 2 * (lane & 3);
                    const float z0 = acc[mt][nt][hf * 2]     + b2p[c];
                    const float z1 = acc[mt][nt][hf * 2 + 1] + b2p[c + 1];
                    const float t0 = ftanh(z0), t1 = ftanh(z1);
                    const float g0 = w3p[c]     * (1.0f - t0 * t0);
                    const float g1 = w3p[c + 1] * (1.0f - t1 * t1);
                    *(uint32_t*)(smem + G2_OF + helem(row, c)) = packh2(g0, g1);
                }
            }
        __syncthreads();

        // ---- 5. GEMM2: G1pre = G2 @ W2^T (B non-trans on [j][k]) ----
        gemm_tile<false>(sb, G2_OF, BB_HI, BB_LO, mbase, nbase, lane, acc);

        // ---- 6. epilogue 2: h1 from H1 buf; pf_i = sum_j W1[i][j]*g1[j] ----
        #pragma unroll
        for (int mt = 0; mt < 2; mt++)
            #pragma unroll
            for (int hf = 0; hf < 2; hf++) {
                const int row = mbase + mt * 16 + (lane >> 2) + hf * 8;
                float pf0 = 0.f, pf1 = 0.f, pf2 = 0.f, pf3 = 0.f;
                #pragma unroll
                for (int nt = 0; nt < 4; nt++) {
                    const int c = nbase + nt * 8 + 2 * (lane & 3);
                    const __half2 hh = *(const __half2*)(smem + H1_OF + helem(row, c));
                    const float2 fh = __half22float2(hh);
                    const float hv[2] = {fh.x, fh.y};
                    #pragma unroll
                    for (int e = 0; e < 2; e++) {
                        const int j = c + e;
                        const float pre = acc[mt][nt][hf * 2 + e];
                        const float h = hv[e];
                        const float g1 = (1.0f - h * h) * pre;
                        const float a0 = w1p[j],       a1 = w1p[128 + j];
                        const float a2 = w1p[256 + j], a3 = w1p[384 + j];
                        pf0 = fmaf(a0, g1, pf0); pf1 = fmaf(a1, g1, pf1);
                        pf2 = fmaf(a2, g1, pf2); pf3 = fmaf(a3, g1, pf3);
                    }
                }
                pf0 += __shfl_xor_sync(0xffffffffu, pf0, 1);
                pf1 += __shfl_xor_sync(0xffffffffu, pf1, 1);
                pf2 += __shfl_xor_sync(0xffffffffu, pf2, 1);
                pf3 += __shfl_xor_sync(0xffffffffu, pf3, 1);
                pf0 += __shfl_xor_sync(0xffffffffu, pf0, 2);
                pf1 += __shfl_xor_sync(0xffffffffu, pf1, 2);
                pf2 += __shfl_xor_sync(0xffffffffu, pf2, 2);
                pf3 += __shfl_xor_sync(0xffffffffu, pf3, 2);
                if ((lane & 3) == 0)
                    *(float4*)(pfb + (ng * 64 + row) * 4) =
                        make_float4(pf0, pf1, pf2, pf3);
            }
        __syncthreads();

        // ---- 7. combine partials + analytic closure + 2x2 solve ----
        if (tid < 64) {
            const int gidx = (t << 6) + tid;
            if (gidx < B) {
                float p0 = 0.f, p1 = 0.f, p2 = 0.f, p3 = 0.f;
                #pragma unroll
                for (int q = 0; q < 4; q++) {
                    const float4 v = *(const float4*)(pfb + (q * 64 + tid) * 4);
                    p0 += v.x; p1 += v.y; p2 += v.z; p3 += v.w;
                }
                const float* tr = trig + tid * 8;
                const float s1 = tr[0], c1 = tr[1], s2 = tr[2], c2 = tr[3];
                const float w1v = tr[4], w2v = tr[5];
                const float sd = s1 * c2 - c1 * s2;
                const float cd = c1 * c2 + s1 * s2;
                const float dV1 = p0 * c1 - p1 * s1;
                const float dV2 = p2 * c2 - p3 * s2;
                const float dw = w2v - w1v;
                const float rhs1 = -w1v * w2v * sd - dV1 - w2v * sd * dw;
                const float rhs2 =  w1v * w2v * sd - dV2 - w1v * sd * dw;
                const float det = 2.0f - cd * cd;
                const float inv = __fdividef(1.0f, det);
                const float q1 = (rhs1 - cd * rhs2) * inv;
                const float q2 = (2.0f * rhs2 - cd * rhs1) * inv;
                reinterpret_cast<float4*>(out)[gidx] = make_float4(w1v, w2v, q1, q2);
            }
        }
        __syncthreads();
    }
}

extern "C" void kernel_launch(void* const* d_in, const int* in_sizes, int n_in,
                              void* d_out, int out_size)
{
    const float* X  = (const float*)d_in[0];
    const float* W1 = (const float*)d_in[1];
    const float* b1 = (const float*)d_in[2];
    const float* W2 = (const float*)d_in[3];
    const float* b2 = (const float*)d_in[4];
    const float* W3 = (const float*)d_in[5];
    float* out = (float*)d_out;
    const int B = in_sizes[0] / 4;

    cudaFuncSetAttribute(lnn_kernel,
                         cudaFuncAttributeMaxDynamicSharedMemorySize,
                         SMEM_TOTAL);
    lnn_kernel<<<296, NTHR, SMEM_TOTAL>>>(X, W1, b1, W2, b2, W3, out, B);
}

// round 11
// speedup vs baseline: 3.8682x; 1.1382x over previous
#include <cuda_runtime.h>
#include <cuda_fp16.h>
#include <cstdint>

#define NTHR 256

// ---- shared memory byte offsets ----
#define BB_HI 0                 // W2 [j][k] fp16 hi (both GEMMs), 32KB
#define BB_LO (32*1024)         // W2 [j][k] fp16 residual lo, 32KB
#define H1_OF (64*1024)         // H1 tile [s][j] fp16, 64 rows, 16KB
#define G2_OF (80*1024)         // G2 tile [s][k] fp16, 64 rows, 16KB
#define OW1   (96*1024)         // 4*128 floats
#define OB1   (OW1 + 2048)
#define OB2   (OB1 + 512)
#define OW3   (OB2 + 512)
#define OTRIG (OW3 + 512)       // 64 * 8 floats = 2KB
#define OPF   (OTRIG + 64*8*4)  // 4 * 64 * 4 floats = 4KB
#define SMEM_TOTAL (OPF + 4*64*4*4)

__device__ __forceinline__ uint32_t smem_u32(const void* p) {
    uint32_t a;
    asm("{ .reg .u64 t; cvta.to.shared.u64 t, %1; cvt.u32.u64 %0, t; }"
        : "=r"(a) : "l"(p));
    return a;
}
// single-MUFU hardware tanh
__device__ __forceinline__ float ftanh(float x) {
    float y;
    asm("tanh.approx.f32 %0, %1;" : "=f"(y) : "f"(x));
    return y;
}
// swizzled byte offset of 16B chunk (row r, chunk) in a [rows]x128 fp16 tile
__device__ __forceinline__ uint32_t swz(int r, int chunk) {
    return (uint32_t)((r << 8) + (((chunk ^ (r & 7)) & 15) << 4));
}
__device__ __forceinline__ uint32_t helem(int r, int c) {
    return swz(r, c >> 3) + ((c & 7) << 1);
}
__device__ __forceinline__ uint32_t packh2(float x0, float x1) {
    const __half2 h = __floats2half2_rn(x0, x1);
    return *(const uint32_t*)&h;
}
__device__ __forceinline__ void ldsm4(uint32_t& r0, uint32_t& r1,
                                      uint32_t& r2, uint32_t& r3, uint32_t a) {
    asm volatile("ldmatrix.sync.aligned.m8n8.x4.shared.b16 {%0,%1,%2,%3}, [%4];"
                 : "=r"(r0), "=r"(r1), "=r"(r2), "=r"(r3) : "r"(a));
}
__device__ __forceinline__ void ldsm4t(uint32_t& r0, uint32_t& r1,
                                       uint32_t& r2, uint32_t& r3, uint32_t a) {
    asm volatile("ldmatrix.sync.aligned.m8n8.x4.trans.shared.b16 {%0,%1,%2,%3}, [%4];"
                 : "=r"(r0), "=r"(r1), "=r"(r2), "=r"(r3) : "r"(a));
}
__device__ __forceinline__ void mma16816(float d[4],
                                         uint32_t a0, uint32_t a1,
                                         uint32_t a2, uint32_t a3,
                                         uint32_t b0, uint32_t b1) {
    asm volatile(
        "mma.sync.aligned.m16n8k16.row.col.f32.f16.f16.f32 "
        "{%0,%1,%2,%3}, {%4,%5,%6,%7}, {%8,%9}, {%0,%1,%2,%3};"
        : "+f"(d[0]), "+f"(d[1]), "+f"(d[2]), "+f"(d[3])
        : "r"(a0), "r"(a1), "r"(a2), "r"(a3), "r"(b0), "r"(b1));
}

// D(64x128) = A(64x128) @ op(B); A plain fp16, B split hi+lo (2-term).
// 8 warps: warp computes m32 x n32. TRANSB: B memory [kdim][n]; else [n][kdim].
// hi-pass then lo-pass per k-step: accumulator reuse distance = 8 MMAs.
template <bool TRANSB>
__device__ __forceinline__ void gemm_tile(uint32_t sb, uint32_t Aoff,
                                          uint32_t Bh, uint32_t Bl,
                                          int mbase, int nbase, int lane,
                                          float acc[2][4][4]) {
    #pragma unroll
    for (int mt = 0; mt < 2; mt++)
        #pragma unroll
        for (int nt = 0; nt < 4; nt++)
            #pragma unroll
            for (int e = 0; e < 4; e++) acc[mt][nt][e] = 0.0f;

    #pragma unroll
    for (int k = 0; k < 8; k++) {
        const int cb = k * 2;
        uint32_t aH[2][4];
        #pragma unroll
        for (int mt = 0; mt < 2; mt++) {
            const int r = mbase + mt * 16 + (lane & 15);
            const uint32_t off = swz(r, cb + (lane >> 4));
            ldsm4(aH[mt][0], aH[mt][1], aH[mt][2], aH[mt][3], sb + Aoff + off);
        }
        uint32_t bH[4][2], bL[4][2];
        #pragma unroll
        for (int p = 0; p < 2; p++) {
            const int ntl   = 2 * p + ((lane >> 4) & 1);
            const int khalf = (lane >> 3) & 1;
            uint32_t off;
            if (TRANSB) {
                const int r = k * 16 + khalf * 8 + (lane & 7);
                off = swz(r, (nbase + ntl * 8) >> 3);
                ldsm4t(bH[2*p][0], bH[2*p][1], bH[2*p+1][0], bH[2*p+1][1],
                       sb + Bh + off);
                ldsm4t(bL[2*p][0], bL[2*p][1], bL[2*p+1][0], bL[2*p+1][1],
                       sb + Bl + off);
            } else {
                const int r = nbase + ntl * 8 + (lane & 7);
                off = swz(r, cb + khalf);
                ldsm4(bH[2*p][0], bH[2*p][1], bH[2*p+1][0], bH[2*p+1][1],
                      sb + Bh + off);
                ldsm4(bL[2*p][0], bL[2*p][1], bL[2*p+1][0], bL[2*p+1][1],
                      sb + Bl + off);
            }
        }
        // hi pass (8 independent MMAs), then lo pass
        #pragma unroll
        for (int mt = 0; mt < 2; mt++)
            #pragma unroll
            for (int nt = 0; nt < 4; nt++)
                mma16816(acc[mt][nt], aH[mt][0], aH[mt][1], aH[mt][2], aH[mt][3],
                         bH[nt][0], bH[nt][1]);
        #pragma unroll
        for (int mt = 0; mt < 2; mt++)
            #pragma unroll
            for (int nt = 0; nt < 4; nt++)
                mma16816(acc[mt][nt], aH[mt][0], aH[mt][1], aH[mt][2], aH[mt][3],
                         bL[nt][0], bL[nt][1]);
    }
}

__global__ void __launch_bounds__(NTHR, 2)
lnn_kernel(const float* __restrict__ X,
           const float* __restrict__ W1, const float* __restrict__ b1,
           const float* __restrict__ W2, const float* __restrict__ b2,
           const float* __restrict__ W3,
           float* __restrict__ out, int B)
{
    extern __shared__ char smem[];
    const uint32_t sb = smem_u32(smem);
    const int tid  = threadIdx.x;
    const int wid  = tid >> 5;
    const int lane = tid & 31;

    // ---- stage W2 split-fp16 (single [j][k] layout) ----
    for (int idx = tid; idx < 128 * 128; idx += NTHR) {
        const int j = idx >> 7, k = idx & 127;
        const float v = W2[idx];
        const __half h = __float2half_rn(v);
        const __half l = __float2half_rn(v - __half2float(h));
        const uint32_t ob = helem(j, k);
        *(uint16_t*)(smem + BB_HI + ob) = __half_as_ushort(h);
        *(uint16_t*)(smem + BB_LO + ob) = __half_as_ushort(l);
    }
    {
        float* w1s = (float*)(smem + OW1);
        for (int i = tid; i < 512; i += NTHR) w1s[i] = W1[i];
        float* d1 = (float*)(smem + OB1);
        float* d2 = (float*)(smem + OB2);
        float* d3 = (float*)(smem + OW3);
        for (int i = tid; i < 128; i += NTHR) {
            d1[i] = b1[i]; d2[i] = b2[i]; d3[i] = W3[i];
        }
    }
    __syncthreads();

    const float* w1p = (const float*)(smem + OW1);
    const float* b1p = (const float*)(smem + OB1);
    const float* b2p = (const float*)(smem + OB2);
    const float* w3p = (const float*)(smem + OW3);
    float* trig = (float*)(smem + OTRIG);
    float* pfb  = (float*)(smem + OPF);

    const int mg = wid >> 2, ng = wid & 3;     // 2 x 4 warp grid
    const int mbase = mg * 32, nbase = ng * 32;

    const int nTiles = (B + 63) >> 6;          // 64-sample tiles
    for (int t = blockIdx.x; t < nTiles; t += gridDim.x) {
        // ---- 1. trig staging ----
        if (tid < 64) {
            const int g = (t << 6) + tid;
            if (g < B) {
                const float4 x = reinterpret_cast<const float4*>(X)[g];
                float s1, c1, s2, c2;
                __sincosf(x.x, &s1, &c1);
                __sincosf(x.y, &s2, &c2);
                float* tr = trig + tid * 8;
                tr[0] = s1; tr[1] = c1; tr[2] = s2; tr[3] = c2;
                tr[4] = x.z; tr[5] = x.w;
            }
        }
        __syncthreads();

        // ---- 2. layer 1: H1 = tanh(feat @ W1 + b1) -> H1 buf (fp16) ----
        {
            const int s = tid & 63;
            const int q = tid >> 6;            // 0..3, owns chunks q*4..q*4+3
            const float* tr = trig + s * 8;
            const float s1 = tr[0], c1 = tr[1], s2 = tr[2], c2 = tr[3];
            #pragma unroll
            for (int qq = 0; qq < 4; qq++) {
                const int cc = q * 4 + qq;
                uint32_t hw[4];
                #pragma unroll
                for (int p = 0; p < 4; p++) {
                    const int j = cc * 8 + p * 2;
                    float z0 = b1p[j], z1 = b1p[j + 1];
                    z0 = fmaf(s1, w1p[j], z0);       z1 = fmaf(s1, w1p[j + 1], z1);
                    z0 = fmaf(c1, w1p[128 + j], z0); z1 = fmaf(c1, w1p[129 + j], z1);
                    z0 = fmaf(s2, w1p[256 + j], z0); z1 = fmaf(s2, w1p[257 + j], z1);
                    z0 = fmaf(c2, w1p[384 + j], z0); z1 = fmaf(c2, w1p[385 + j], z1);
                    hw[p] = packh2(ftanh(z0), ftanh(z1));
                }
                const uint32_t off = swz(s, cc);
                *(uint4*)(smem + H1_OF + off) = make_uint4(hw[0], hw[1], hw[2], hw[3]);
            }
        }
        __syncthreads();

        // ---- 3. GEMM1: Z2 = H1 @ W2 (B via trans ldmatrix on [j][k]) ----
        float acc[2][4][4];
        gemm_tile<true>(sb, H1_OF, BB_HI, BB_LO, mbase, nbase, lane, acc);

        // ---- 4. epilogue 1: G2 = W3*(1-tanh(Z2+b2)^2) -> G2 buf (fp16) ----
        #pragma unroll
        for (int mt = 0; mt < 2; mt++)
            #pragma unroll
            for (int hf = 0; hf < 2; hf++) {
                const int row = mbase + mt * 16 + (lane >> 2) + hf * 8;
                #pragma unroll
                for (int nt = 0; nt < 4; nt++) {
                    const int c = nbase + nt * 8 + 2 * (lane & 3);
                    const float z0 = acc[mt][nt][hf * 2]     + b2p[c];
                    const float z1 = acc[mt][nt][hf * 2 + 1] + b2p[c + 1];
                    const float t0 = ftanh(z0), t1 = ftanh(z1);
                    const float g0 = w3p[c]     * (1.0f - t0 * t0);
                    const float g1 = w3p[c + 1] * (1.0f - t1 * t1);
                    *(uint32_t*)(smem + G2_OF + helem(row, c)) = packh2(g0, g1);
                }
            }
        __syncthreads();

        // ---- 5. GEMM2: G1pre = G2 @ W2^T (B non-trans on [j][k]) ----
        gemm_tile<false>(sb, G2_OF, BB_HI, BB_LO, mbase, nbase, lane, acc);

        // ---- 6. epilogue 2: h1 from H1 buf; pf_i = sum_j W1[i][j]*g1[j] ----
        #pragma unroll
        for (int mt = 0; mt < 2; mt++)
            #pragma unroll
            for (int hf = 0; hf < 2; hf++) {
                const int row = mbase + mt * 16 + (lane >> 2) + hf * 8;
                float pf0 = 0.f, pf1 = 0.f, pf2 = 0.f, pf3 = 0.f;
                #pragma unroll
                for (int nt = 0; nt < 4; nt++) {
                    const int c = nbase + nt * 8 + 2 * (lane & 3);
                    const __half2 hh = *(const __half2*)(smem + H1_OF + helem(row, c));
                    const float2 fh = __half22float2(hh);
                    const float hv[2] = {fh.x, fh.y};
                    #pragma unroll
                    for (int e = 0; e < 2; e++) {
                        const int j = c + e;
                        const float pre = acc[mt][nt][hf * 2 + e];
                        const float h = hv[e];
                        const float g1 = (1.0f - h * h) * pre;
                        const float a0 = w1p[j],       a1 = w1p[128 + j];
                        const float a2 = w1p[256 + j], a3 = w1p[384 + j];
                        pf0 = fmaf(a0, g1, pf0); pf1 = fmaf(a1, g1, pf1);
                        pf2 = fmaf(a2, g1, pf2); pf3 = fmaf(a3, g1, pf3);
                    }
                }
                pf0 += __shfl_xor_sync(0xffffffffu, pf0, 1);
                pf1 += __shfl_xor_sync(0xffffffffu, pf1, 1);
                pf2 += __shfl_xor_sync(0xffffffffu, pf2, 1);
                pf3 += __shfl_xor_sync(0xffffffffu, pf3, 1);
                pf0 += __shfl_xor_sync(0xffffffffu, pf0, 2);
                pf1 += __shfl_xor_sync(0xffffffffu, pf1, 2);
                pf2 += __shfl_xor_sync(0xffffffffu, pf2, 2);
                pf3 += __shfl_xor_sync(0xffffffffu, pf3, 2);
                if ((lane & 3) == 0)
                    *(float4*)(pfb + (ng * 64 + row) * 4) =
                        make_float4(pf0, pf1, pf2, pf3);
            }
        __syncthreads();

        // ---- 7. combine partials + analytic closure + 2x2 solve ----
        if (tid < 64) {
            const int gidx = (t << 6) + tid;
            if (gidx < B) {
                float p0 = 0.f, p1 = 0.f, p2 = 0.f, p3 = 0.f;
                #pragma unroll
                for (int q = 0; q < 4; q++) {
                    const float4 v = *(const float4*)(pfb + (q * 64 + tid) * 4);
                    p0 += v.x; p1 += v.y; p2 += v.z; p3 += v.w;
                }
                const float* tr = trig + tid * 8;
                const float s1 = tr[0], c1 = tr[1], s2 = tr[2], c2 = tr[3];
                const float w1v = tr[4], w2v = tr[5];
                const float sd = s1 * c2 - c1 * s2;
                const float cd = c1 * c2 + s1 * s2;
                const float dV1 = p0 * c1 - p1 * s1;
                const float dV2 = p2 * c2 - p3 * s2;
                const float dw = w2v - w1v;
                const float rhs1 = -w1v * w2v * sd - dV1 - w2v * sd * dw;
                const float rhs2 =  w1v * w2v * sd - dV2 - w1v * sd * dw;
                const float det = 2.0f - cd * cd;
                const float inv = __fdividef(1.0f, det);
                const float q1 = (rhs1 - cd * rhs2) * inv;
                const float q2 = (2.0f * rhs2 - cd * rhs1) * inv;
                reinterpret_cast<float4*>(out)[gidx] = make_float4(w1v, w2v, q1, q2);
            }
        }
        __syncthreads();
    }
}

extern "C" void kernel_launch(void* const* d_in, const int* in_sizes, int n_in,
                              void* d_out, int out_size)
{
    const float* X  = (const float*)d_in[0];
    const float* W1 = (const float*)d_in[1];
    const float* b1 = (const float*)d_in[2];
    const float* W2 = (const float*)d_in[3];
    const float* b2 = (const float*)d_in[4];
    const float* W3 = (const float*)d_in[5];
    float* out = (float*)d_out;
    const int B = in_sizes[0] / 4;

    cudaFuncSetAttribute(lnn_kernel,
                         cudaFuncAttributeMaxDynamicSharedMemorySize,
                         SMEM_TOTAL);
    lnn_kernel<<<296, NTHR, SMEM_TOTAL>>>(X, W1, b1, W2, b2, W3, out, B);
}

// round 12
// speedup vs baseline: 4.6604x; 1.2048x over previous
#include <cuda_runtime.h>
#include <cuda_fp16.h>
#include <cstdint>

#define NTHR 256

// ---- shared memory byte offsets ----
#define BB_HI 0                 // W2 [j][k] fp16 (both GEMMs), 32KB
#define H1_OF (32*1024)         // H1 tile [s][j] fp16, 64 rows, 16KB
#define G2_OF (48*1024)         // G2 tile [s][k] fp16, 64 rows, 16KB
#define OW1   (64*1024)         // 4*128 floats
#define OB1   (OW1 + 2048)
#define OB2   (OB1 + 512)
#define OW3   (OB2 + 512)
#define OTRIG (OW3 + 512)       // 64 * 8 floats = 2KB
#define OPF   (OTRIG + 64*8*4)  // 4 * 64 * 4 floats = 4KB
#define SMEM_TOTAL (OPF + 4*64*4*4)

__device__ __forceinline__ uint32_t smem_u32(const void* p) {
    uint32_t a;
    asm("{ .reg .u64 t; cvta.to.shared.u64 t, %1; cvt.u32.u64 %0, t; }"
        : "=r"(a) : "l"(p));
    return a;
}
__device__ __forceinline__ float ftanh(float x) {
    float y;
    asm("tanh.approx.f32 %0, %1;" : "=f"(y) : "f"(x));
    return y;
}
// swizzled byte offset of 16B chunk (row r, chunk) in a [rows]x128 fp16 tile
__device__ __forceinline__ uint32_t swz(int r, int chunk) {
    return (uint32_t)((r << 8) + (((chunk ^ (r & 7)) & 15) << 4));
}
__device__ __forceinline__ uint32_t helem(int r, int c) {
    return swz(r, c >> 3) + ((c & 7) << 1);
}
__device__ __forceinline__ uint32_t packh2(float x0, float x1) {
    const __half2 h = __floats2half2_rn(x0, x1);
    return *(const uint32_t*)&h;
}
__device__ __forceinline__ void ldsm4(uint32_t& r0, uint32_t& r1,
                                      uint32_t& r2, uint32_t& r3, uint32_t a) {
    asm volatile("ldmatrix.sync.aligned.m8n8.x4.shared.b16 {%0,%1,%2,%3}, [%4];"
                 : "=r"(r0), "=r"(r1), "=r"(r2), "=r"(r3) : "r"(a));
}
__device__ __forceinline__ void ldsm4t(uint32_t& r0, uint32_t& r1,
                                       uint32_t& r2, uint32_t& r3, uint32_t a) {
    asm volatile("ldmatrix.sync.aligned.m8n8.x4.trans.shared.b16 {%0,%1,%2,%3}, [%4];"
                 : "=r"(r0), "=r"(r1), "=r"(r2), "=r"(r3) : "r"(a));
}
__device__ __forceinline__ void stsm4(uint32_t a, uint32_t r0, uint32_t r1,
                                      uint32_t r2, uint32_t r3) {
    asm volatile("stmatrix.sync.aligned.m8n8.x4.shared.b16 [%0], {%1,%2,%3,%4};"
                 :: "r"(a), "r"(r0), "r"(r1), "r"(r2), "r"(r3) : "memory");
}
__device__ __forceinline__ void mma16816(float d[4],
                                         uint32_t a0, uint32_t a1,
                                         uint32_t a2, uint32_t a3,
                                         uint32_t b0, uint32_t b1) {
    asm volatile(
        "mma.sync.aligned.m16n8k16.row.col.f32.f16.f16.f32 "
        "{%0,%1,%2,%3}, {%4,%5,%6,%7}, {%8,%9}, {%0,%1,%2,%3};"
        : "+f"(d[0]), "+f"(d[1]), "+f"(d[2]), "+f"(d[3])
        : "r"(a0), "r"(a1), "r"(a2), "r"(a3), "r"(b0), "r"(b1));
}

// D(64x128) = A(64x128) @ op(B); plain fp16 single term.
// 8 warps: warp computes m32 x n32. TRANSB: B memory [kdim][n]; else [n][kdim].
template <bool TRANSB>
__device__ __forceinline__ void gemm_tile(uint32_t sb, uint32_t Aoff, uint32_t Bo,
                                          int mbase, int nbase, int lane,
                                          float acc[2][4][4]) {
    #pragma unroll
    for (int mt = 0; mt < 2; mt++)
        #pragma unroll
        for (int nt = 0; nt < 4; nt++)
            #pragma unroll
            for (int e = 0; e < 4; e++) acc[mt][nt][e] = 0.0f;

    #pragma unroll
    for (int k = 0; k < 8; k++) {
        const int cb = k * 2;
        uint32_t aH[2][4];
        #pragma unroll
        for (int mt = 0; mt < 2; mt++) {
            const int r = mbase + mt * 16 + (lane & 15);
            const uint32_t off = swz(r, cb + (lane >> 4));
            ldsm4(aH[mt][0], aH[mt][1], aH[mt][2], aH[mt][3], sb + Aoff + off);
        }
        uint32_t bH[4][2];
        #pragma unroll
        for (int p = 0; p < 2; p++) {
            const int ntl   = 2 * p + ((lane >> 4) & 1);
            const int khalf = (lane >> 3) & 1;
            if (TRANSB) {
                const int r = k * 16 + khalf * 8 + (lane & 7);
                const uint32_t off = swz(r, (nbase + ntl * 8) >> 3);
                ldsm4t(bH[2*p][0], bH[2*p][1], bH[2*p+1][0], bH[2*p+1][1],
                       sb + Bo + off);
            } else {
                const int r = nbase + ntl * 8 + (lane & 7);
                const uint32_t off = swz(r, cb + khalf);
                ldsm4(bH[2*p][0], bH[2*p][1], bH[2*p+1][0], bH[2*p+1][1],
                      sb + Bo + off);
            }
        }
        #pragma unroll
        for (int mt = 0; mt < 2; mt++)
            #pragma unroll
            for (int nt = 0; nt < 4; nt++)
                mma16816(acc[mt][nt], aH[mt][0], aH[mt][1], aH[mt][2], aH[mt][3],
                         bH[nt][0], bH[nt][1]);
    }
}

__global__ void __launch_bounds__(NTHR, 2)
lnn_kernel(const float* __restrict__ X,
           const float* __restrict__ W1, const float* __restrict__ b1,
           const float* __restrict__ W2, const float* __restrict__ b2,
           const float* __restrict__ W3,
           float* __restrict__ out, int B)
{
    extern __shared__ char smem[];
    const uint32_t sb = smem_u32(smem);
    const int tid  = threadIdx.x;
    const int wid  = tid >> 5;
    const int lane = tid & 31;

    // ---- stage W2 fp16 (single [j][k] layout) ----
    for (int idx = tid; idx < 128 * 128; idx += NTHR) {
        const int j = idx >> 7, k = idx & 127;
        const __half h = __float2half_rn(W2[idx]);
        *(uint16_t*)(smem + BB_HI + helem(j, k)) = __half_as_ushort(h);
    }
    {
        float* w1s = (float*)(smem + OW1);
        for (int i = tid; i < 512; i += NTHR) w1s[i] = W1[i];
        float* d1 = (float*)(smem + OB1);
        float* d2 = (float*)(smem + OB2);
        float* d3 = (float*)(smem + OW3);
        for (int i = tid; i < 128; i += NTHR) {
            d1[i] = b1[i]; d2[i] = b2[i]; d3[i] = W3[i];
        }
    }
    __syncthreads();

    const float* w1p = (const float*)(smem + OW1);
    const float* b1p = (const float*)(smem + OB1);
    const float* b2p = (const float*)(smem + OB2);
    const float* w3p = (const float*)(smem + OW3);
    float* trig = (float*)(smem + OTRIG);
    float* pfb  = (float*)(smem + OPF);

    const int mg = wid >> 2, ng = wid & 3;     // 2 x 4 warp grid
    const int mbase = mg * 32, nbase = ng * 32;

    const int nTiles = (B + 63) >> 6;          // 64-sample tiles
    for (int t = blockIdx.x; t < nTiles; t += gridDim.x) {
        // ---- 1. trig staging ----
        if (tid < 64) {
            const int g = (t << 6) + tid;
            if (g < B) {
                const float4 x = reinterpret_cast<const float4*>(X)[g];
                float s1, c1, s2, c2;
                __sincosf(x.x, &s1, &c1);
                __sincosf(x.y, &s2, &c2);
                float* tr = trig + tid * 8;
                tr[0] = s1; tr[1] = c1; tr[2] = s2; tr[3] = c2;
                tr[4] = x.z; tr[5] = x.w;
            }
        }
        __syncthreads();

        // ---- 2. layer 1: H1 = tanh(feat @ W1 + b1) -> H1 buf (fp16) ----
        {
            const int s = tid & 63;
            const int q = tid >> 6;            // 0..3, owns chunks q*4..q*4+3
            const float* tr = trig + s * 8;
            const float s1 = tr[0], c1 = tr[1], s2 = tr[2], c2 = tr[3];
            #pragma unroll
            for (int qq = 0; qq < 4; qq++) {
                const int cc = q * 4 + qq;
                uint32_t hw[4];
                #pragma unroll
                for (int p = 0; p < 4; p++) {
                    const int j = cc * 8 + p * 2;
                    float z0 = b1p[j], z1 = b1p[j + 1];
                    z0 = fmaf(s1, w1p[j], z0);       z1 = fmaf(s1, w1p[j + 1], z1);
                    z0 = fmaf(c1, w1p[128 + j], z0); z1 = fmaf(c1, w1p[129 + j], z1);
                    z0 = fmaf(s2, w1p[256 + j], z0); z1 = fmaf(s2, w1p[257 + j], z1);
                    z0 = fmaf(c2, w1p[384 + j], z0); z1 = fmaf(c2, w1p[385 + j], z1);
                    hw[p] = packh2(ftanh(z0), ftanh(z1));
                }
                const uint32_t off = swz(s, cc);
                *(uint4*)(smem + H1_OF + off) = make_uint4(hw[0], hw[1], hw[2], hw[3]);
            }
        }
        __syncthreads();

        // ---- 3. GEMM1: Z2 = H1 @ W2 (B via trans ldmatrix on [j][k]) ----
        float acc[2][4][4];
        gemm_tile<true>(sb, H1_OF, BB_HI, mbase, nbase, lane, acc);

        // ---- 4. epilogue 1: G2 = W3*(1-tanh(Z2+b2)^2) -> G2 buf (stmatrix) ----
        #pragma unroll
        for (int mt = 0; mt < 2; mt++)
            #pragma unroll
            for (int hf = 0; hf < 2; hf++) {
                uint32_t rr[4];
                #pragma unroll
                for (int nt = 0; nt < 4; nt++) {
                    const int c = nbase + nt * 8 + 2 * (lane & 3);
                    const float z0 = acc[mt][nt][hf * 2]     + b2p[c];
                    const float z1 = acc[mt][nt][hf * 2 + 1] + b2p[c + 1];
                    const float t0 = ftanh(z0), t1 = ftanh(z1);
                    const float g0 = w3p[c]     * (1.0f - t0 * t0);
                    const float g1 = w3p[c + 1] * (1.0f - t1 * t1);
                    rr[nt] = packh2(g0, g1);
                }
                const int row = mbase + mt * 16 + hf * 8 + (lane & 7);
                const uint32_t addr =
                    sb + G2_OF + swz(row, (nbase >> 3) + (lane >> 3));
                stsm4(addr, rr[0], rr[1], rr[2], rr[3]);
            }
        __syncthreads();

        // ---- 5. GEMM2: G1pre = G2 @ W2^T (B non-trans on [j][k]) ----
        gemm_tile<false>(sb, G2_OF, BB_HI, mbase, nbase, lane, acc);

        // ---- 6. epilogue 2: h1 fragments via ldmatrix; pf_i = sum W1*g1 ----
        #pragma unroll
        for (int mt = 0; mt < 2; mt++)
            #pragma unroll
            for (int hf = 0; hf < 2; hf++) {
                const int lrow = mbase + mt * 16 + hf * 8 + (lane & 7);
                uint32_t hfrag[4];
                ldsm4(hfrag[0], hfrag[1], hfrag[2], hfrag[3],
                      sb + H1_OF + swz(lrow, (nbase >> 3) + (lane >> 3)));
                float pf0 = 0.f, pf1 = 0.f, pf2 = 0.f, pf3 = 0.f;
                #pragma unroll
                for (int nt = 0; nt < 4; nt++) {
                    const int c = nbase + nt * 8 + 2 * (lane & 3);
                    const float2 fh = __half22float2(*(const __half2*)&hfrag[nt]);
                    const float hv[2] = {fh.x, fh.y};
                    #pragma unroll
                    for (int e = 0; e < 2; e++) {
                        const int j = c + e;
                        const float pre = acc[mt][nt][hf * 2 + e];
                        const float h = hv[e];
                        const float g1 = (1.0f - h * h) * pre;
                        const float a0 = w1p[j],       a1 = w1p[128 + j];
                        const float a2 = w1p[256 + j], a3 = w1p[384 + j];
                        pf0 = fmaf(a0, g1, pf0); pf1 = fmaf(a1, g1, pf1);
                        pf2 = fmaf(a2, g1, pf2); pf3 = fmaf(a3, g1, pf3);
                    }
                }
                pf0 += __shfl_xor_sync(0xffffffffu, pf0, 1);
                pf1 += __shfl_xor_sync(0xffffffffu, pf1, 1);
                pf2 += __shfl_xor_sync(0xffffffffu, pf2, 1);
                pf3 += __shfl_xor_sync(0xffffffffu, pf3, 1);
                pf0 += __shfl_xor_sync(0xffffffffu, pf0, 2);
                pf1 += __shfl_xor_sync(0xffffffffu, pf1, 2);
                pf2 += __shfl_xor_sync(0xffffffffu, pf2, 2);
                pf3 += __shfl_xor_sync(0xffffffffu, pf3, 2);
                const int row = mbase + mt * 16 + (lane >> 2) + hf * 8;
                if ((lane & 3) == 0)
                    *(float4*)(pfb + (ng * 64 + row) * 4) =
                        make_float4(pf0, pf1, pf2, pf3);
            }
        __syncthreads();

        // ---- 7. combine partials + analytic closure + 2x2 solve ----
        if (tid < 64) {
            const int gidx = (t << 6) + tid;
            if (gidx < B) {
                float p0 = 0.f, p1 = 0.f, p2 = 0.f, p3 = 0.f;
                #pragma unroll
                for (int q = 0; q < 4; q++) {
                    const float4 v = *(const float4*)(pfb + (q * 64 + tid) * 4);
                    p0 += v.x; p1 += v.y; p2 += v.z; p3 += v.w;
                }
                const float* tr = trig + tid * 8;
                const float s1 = tr[0], c1 = tr[1], s2 = tr[2], c2 = tr[3];
                const float w1v = tr[4], w2v = tr[5];
                const float sd = s1 * c2 - c1 * s2;
                const float cd = c1 * c2 + s1 * s2;
                const float dV1 = p0 * c1 - p1 * s1;
                const float dV2 = p2 * c2 - p3 * s2;
                const float dw = w2v - w1v;
                const float rhs1 = -w1v * w2v * sd - dV1 - w2v * sd * dw;
                const float rhs2 =  w1v * w2v * sd - dV2 - w1v * sd * dw;
                const float det = 2.0f - cd * cd;
                const float inv = __fdividef(1.0f, det);
                const float q1 = (rhs1 - cd * rhs2) * inv;
                const float q2 = (2.0f * rhs2 - cd * rhs1) * inv;
                reinterpret_cast<float4*>(out)[gidx] = make_float4(w1v, w2v, q1, q2);
            }
        }
        __syncthreads();
    }
}

extern "C" void kernel_launch(void* const* d_in, const int* in_sizes, int n_in,
                              void* d_out, int out_size)
{
    const float* X  = (const float*)d_in[0];
    const float* W1 = (const float*)d_in[1];
    const float* b1 = (const float*)d_in[2];
    const float* W2 = (const float*)d_in[3];
    const float* b2 = (const float*)d_in[4];
    const float* W3 = (const float*)d_in[5];
    float* out = (float*)d_out;
    const int B = in_sizes[0] / 4;

    cudaFuncSetAttribute(lnn_kernel,
                         cudaFuncAttributeMaxDynamicSharedMemorySize,
                         SMEM_TOTAL);
    lnn_kernel<<<296, NTHR, SMEM_TOTAL>>>(X, W1, b1, W2, b2, W3, out, B);
}

// round 13
// speedup vs baseline: 5.0534x; 1.0843x over previous
#include <cuda_runtime.h>
#include <cuda_fp16.h>
#include <cstdint>

#define NTHR 256

// ---- shared memory byte offsets ----
#define BB_HI 0                 // W2 [j][k] fp16 (both GEMMs), 32KB
#define H1_OF (32*1024)         // H1 tile [s][j] fp16, 128 rows, 32KB
#define G2_OF (64*1024)         // G2 tile [s][k] fp16, 128 rows, 32KB
#define OW1   (96*1024)         // 4*128 floats
#define OB1   (OW1 + 2048)
#define OB2   (OB1 + 512)
#define OW3   (OB2 + 512)
#define OTRIG (OW3 + 512)       // 128 * 8 floats = 4KB
#define OPF   (OTRIG + 128*8*4) // 4 * 128 * 4 floats = 8KB
#define SMEM_TOTAL (OPF + 4*128*4*4)

__device__ __forceinline__ uint32_t smem_u32(const void* p) {
    uint32_t a;
    asm("{ .reg .u64 t; cvta.to.shared.u64 t, %1; cvt.u32.u64 %0, t; }"
        : "=r"(a) : "l"(p));
    return a;
}
__device__ __forceinline__ float ftanh(float x) {
    float y;
    asm("tanh.approx.f32 %0, %1;" : "=f"(y) : "f"(x));
    return y;
}
// swizzled byte offset of 16B chunk (row r, chunk) in a [rows]x128 fp16 tile
__device__ __forceinline__ uint32_t swz(int r, int chunk) {
    return (uint32_t)((r << 8) + (((chunk ^ (r & 7)) & 15) << 4));
}
__device__ __forceinline__ uint32_t helem(int r, int c) {
    return swz(r, c >> 3) + ((c & 7) << 1);
}
__device__ __forceinline__ uint32_t packh2(float x0, float x1) {
    const __half2 h = __floats2half2_rn(x0, x1);
    return *(const uint32_t*)&h;
}
__device__ __forceinline__ void ldsm4(uint32_t& r0, uint32_t& r1,
                                      uint32_t& r2, uint32_t& r3, uint32_t a) {
    asm volatile("ldmatrix.sync.aligned.m8n8.x4.shared.b16 {%0,%1,%2,%3}, [%4];"
                 : "=r"(r0), "=r"(r1), "=r"(r2), "=r"(r3) : "r"(a));
}
__device__ __forceinline__ void ldsm4t(uint32_t& r0, uint32_t& r1,
                                       uint32_t& r2, uint32_t& r3, uint32_t a) {
    asm volatile("ldmatrix.sync.aligned.m8n8.x4.trans.shared.b16 {%0,%1,%2,%3}, [%4];"
                 : "=r"(r0), "=r"(r1), "=r"(r2), "=r"(r3) : "r"(a));
}
__device__ __forceinline__ void stsm4(uint32_t a, uint32_t r0, uint32_t r1,
                                      uint32_t r2, uint32_t r3) {
    asm volatile("stmatrix.sync.aligned.m8n8.x4.shared.b16 [%0], {%1,%2,%3,%4};"
                 :: "r"(a), "r"(r0), "r"(r1), "r"(r2), "r"(r3) : "memory");
}
__device__ __forceinline__ void mma16816(float d[4],
                                         uint32_t a0, uint32_t a1,
                                         uint32_t a2, uint32_t a3,
                                         uint32_t b0, uint32_t b1) {
    asm volatile(
        "mma.sync.aligned.m16n8k16.row.col.f32.f16.f16.f32 "
        "{%0,%1,%2,%3}, {%4,%5,%6,%7}, {%8,%9}, {%0,%1,%2,%3};"
        : "+f"(d[0]), "+f"(d[1]), "+f"(d[2]), "+f"(d[3])
        : "r"(a0), "r"(a1), "r"(a2), "r"(a3), "r"(b0), "r"(b1));
}

// D(128x128) = A(128x128) @ op(B); plain fp16 single term.
// 8 warps in 2x4 grid: warp computes m64 x n32 (mt=4).
// TRANSB: B memory [kdim][n]; else [n][kdim].
template <bool TRANSB>
__device__ __forceinline__ void gemm_tile(uint32_t sb, uint32_t Aoff, uint32_t Bo,
                                          int mbase, int nbase, int lane,
                                          float acc[4][4][4]) {
    #pragma unroll
    for (int mt = 0; mt < 4; mt++)
        #pragma unroll
        for (int nt = 0; nt < 4; nt++)
            #pragma unroll
            for (int e = 0; e < 4; e++) acc[mt][nt][e] = 0.0f;

    #pragma unroll
    for (int k = 0; k < 8; k++) {
        const int cb = k * 2;
        uint32_t bH[4][2];
        #pragma unroll
        for (int p = 0; p < 2; p++) {
            const int ntl   = 2 * p + ((lane >> 4) & 1);
            const int khalf = (lane >> 3) & 1;
            if (TRANSB) {
                const int r = k * 16 + khalf * 8 + (lane & 7);
                const uint32_t off = swz(r, (nbase + ntl * 8) >> 3);
                ldsm4t(bH[2*p][0], bH[2*p][1], bH[2*p+1][0], bH[2*p+1][1],
                       sb + Bo + off);
            } else {
                const int r = nbase + ntl * 8 + (lane & 7);
                const uint32_t off = swz(r, cb + khalf);
                ldsm4(bH[2*p][0], bH[2*p][1], bH[2*p+1][0], bH[2*p+1][1],
                      sb + Bo + off);
            }
        }
        #pragma unroll
        for (int mt = 0; mt < 4; mt++) {
            uint32_t aH[4];
            const int r = mbase + mt * 16 + (lane & 15);
            const uint32_t off = swz(r, cb + (lane >> 4));
            ldsm4(aH[0], aH[1], aH[2], aH[3], sb + Aoff + off);
            #pragma unroll
            for (int nt = 0; nt < 4; nt++)
                mma16816(acc[mt][nt], aH[0], aH[1], aH[2], aH[3],
                         bH[nt][0], bH[nt][1]);
        }
    }
}

__global__ void __launch_bounds__(NTHR, 2)
lnn_kernel(const float* __restrict__ X,
           const float* __restrict__ W1, const float* __restrict__ b1,
           const float* __restrict__ W2, const float* __restrict__ b2,
           const float* __restrict__ W3,
           float* __restrict__ out, int B)
{
    extern __shared__ char smem[];
    const uint32_t sb = smem_u32(smem);
    const int tid  = threadIdx.x;
    const int wid  = tid >> 5;
    const int lane = tid & 31;

    // ---- stage W2 fp16 (single [j][k] layout) ----
    for (int idx = tid; idx < 128 * 128; idx += NTHR) {
        const int j = idx >> 7, k = idx & 127;
        const __half h = __float2half_rn(W2[idx]);
        *(uint16_t*)(smem + BB_HI + helem(j, k)) = __half_as_ushort(h);
    }
    {
        float* w1s = (float*)(smem + OW1);
        for (int i = tid; i < 512; i += NTHR) w1s[i] = W1[i];
        float* d1 = (float*)(smem + OB1);
        float* d2 = (float*)(smem + OB2);
        float* d3 = (float*)(smem + OW3);
        for (int i = tid; i < 128; i += NTHR) {
            d1[i] = b1[i]; d2[i] = b2[i]; d3[i] = W3[i];
        }
    }
    __syncthreads();

    const float* w1p = (const float*)(smem + OW1);
    const float* b1p = (const float*)(smem + OB1);
    const float* b2p = (const float*)(smem + OB2);
    const float* w3p = (const float*)(smem + OW3);
    float* trig = (float*)(smem + OTRIG);
    float* pfb  = (float*)(smem + OPF);

    const int mg = wid >> 2, ng = wid & 3;     // 2 x 4 warp grid
    const int mbase = mg * 64, nbase = ng * 32;

    const int nTiles = (B + 127) >> 7;         // 128-sample tiles
    for (int t = blockIdx.x; t < nTiles; t += gridDim.x) {
        // ---- 1. trig staging ----
        if (tid < 128) {
            const int g = (t << 7) + tid;
            if (g < B) {
                const float4 x = reinterpret_cast<const float4*>(X)[g];
                float s1, c1, s2, c2;
                __sincosf(x.x, &s1, &c1);
                __sincosf(x.y, &s2, &c2);
                float* tr = trig + tid * 8;
                tr[0] = s1; tr[1] = c1; tr[2] = s2; tr[3] = c2;
                tr[4] = x.z; tr[5] = x.w;
            }
        }
        __syncthreads();

        // ---- 2. layer 1: H1 = tanh(feat @ W1 + b1) -> H1 buf (fp16) ----
        {
            const int s = tid & 127;
            const int q = tid >> 7;            // 0..1, owns chunks q*8..q*8+7
            const float* tr = trig + s * 8;
            const float s1 = tr[0], c1 = tr[1], s2 = tr[2], c2 = tr[3];
            #pragma unroll
            for (int qq = 0; qq < 8; qq++) {
                const int cc = q * 8 + qq;
                uint32_t hw[4];
                #pragma unroll
                for (int p = 0; p < 4; p++) {
                    const int j = cc * 8 + p * 2;
                    float z0 = b1p[j], z1 = b1p[j + 1];
                    z0 = fmaf(s1, w1p[j], z0);       z1 = fmaf(s1, w1p[j + 1], z1);
                    z0 = fmaf(c1, w1p[128 + j], z0); z1 = fmaf(c1, w1p[129 + j], z1);
                    z0 = fmaf(s2, w1p[256 + j], z0); z1 = fmaf(s2, w1p[257 + j], z1);
                    z0 = fmaf(c2, w1p[384 + j], z0); z1 = fmaf(c2, w1p[385 + j], z1);
                    hw[p] = packh2(ftanh(z0), ftanh(z1));
                }
                const uint32_t off = swz(s, cc);
                *(uint4*)(smem + H1_OF + off) = make_uint4(hw[0], hw[1], hw[2], hw[3]);
            }
        }
        __syncthreads();

        // ---- 3. GEMM1: Z2 = H1 @ W2 (B via trans ldmatrix on [j][k]) ----
        float acc[4][4][4];
        gemm_tile<true>(sb, H1_OF, BB_HI, mbase, nbase, lane, acc);

        // ---- 4. epilogue 1: G2 = W3*(1-tanh(Z2+b2)^2) -> G2 buf (stmatrix) ----
        #pragma unroll
        for (int mt = 0; mt < 4; mt++)
            #pragma unroll
            for (int hf = 0; hf < 2; hf++) {
                uint32_t rr[4];
                #pragma unroll
                for (int nt = 0; nt < 4; nt++) {
                    const int c = nbase + nt * 8 + 2 * (lane & 3);
                    const float z0 = acc[mt][nt][hf * 2]     + b2p[c];
                    const float z1 = acc[mt][nt][hf * 2 + 1] + b2p[c + 1];
                    const float t0 = ftanh(z0), t1 = ftanh(z1);
                    const float g0 = w3p[c]     * (1.0f - t0 * t0);
                    const float g1 = w3p[c + 1] * (1.0f - t1 * t1);
                    rr[nt] = packh2(g0, g1);
                }
                const int row = mbase + mt * 16 + hf * 8 + (lane & 7);
                const uint32_t addr =
                    sb + G2_OF + swz(row, (nbase >> 3) + (lane >> 3));
                stsm4(addr, rr[0], rr[1], rr[2], rr[3]);
            }
        __syncthreads();

        // ---- 5. GEMM2: G1pre = G2 @ W2^T (B non-trans on [j][k]) ----
        gemm_tile<false>(sb, G2_OF, BB_HI, mbase, nbase, lane, acc);

        // ---- 6. epilogue 2: h1 fragments via ldmatrix; pf_i = sum W1*g1 ----
        #pragma unroll
        for (int mt = 0; mt < 4; mt++)
            #pragma unroll
            for (int hf = 0; hf < 2; hf++) {
                const int lrow = mbase + mt * 16 + hf * 8 + (lane & 7);
                uint32_t hfrag[4];
                ldsm4(hfrag[0], hfrag[1], hfrag[2], hfrag[3],
                      sb + H1_OF + swz(lrow, (nbase >> 3) + (lane >> 3)));
                float pf0 = 0.f, pf1 = 0.f, pf2 = 0.f, pf3 = 0.f;
                #pragma unroll
                for (int nt = 0; nt < 4; nt++) {
                    const int c = nbase + nt * 8 + 2 * (lane & 3);
                    const float2 fh = __half22float2(*(const __half2*)&hfrag[nt]);
                    const float hv[2] = {fh.x, fh.y};
                    #pragma unroll
                    for (int e = 0; e < 2; e++) {
                        const int j = c + e;
                        const float pre = acc[mt][nt][hf * 2 + e];
                        const float h = hv[e];
                        const float g1 = (1.0f - h * h) * pre;
                        const float a0 = w1p[j],       a1 = w1p[128 + j];
                        const float a2 = w1p[256 + j], a3 = w1p[384 + j];
                        pf0 = fmaf(a0, g1, pf0); pf1 = fmaf(a1, g1, pf1);
                        pf2 = fmaf(a2, g1, pf2); pf3 = fmaf(a3, g1, pf3);
                    }
                }
                pf0 += __shfl_xor_sync(0xffffffffu, pf0, 1);
                pf1 += __shfl_xor_sync(0xffffffffu, pf1, 1);
                pf2 += __shfl_xor_sync(0xffffffffu, pf2, 1);
                pf3 += __shfl_xor_sync(0xffffffffu, pf3, 1);
                pf0 += __shfl_xor_sync(0xffffffffu, pf0, 2);
                pf1 += __shfl_xor_sync(0xffffffffu, pf1, 2);
                pf2 += __shfl_xor_sync(0xffffffffu, pf2, 2);
                pf3 += __shfl_xor_sync(0xffffffffu, pf3, 2);
                const int row = mbase + mt * 16 + (lane >> 2) + hf * 8;
                if ((lane & 3) == 0)
                    *(float4*)(pfb + (ng * 128 + row) * 4) =
                        make_float4(pf0, pf1, pf2, pf3);
            }
        __syncthreads();

        // ---- 7. combine partials + analytic closure + 2x2 solve ----
        if (tid < 128) {
            const int gidx = (t << 7) + tid;
            if (gidx < B) {
                float p0 = 0.f, p1 = 0.f, p2 = 0.f, p3 = 0.f;
                #pragma unroll
                for (int q = 0; q < 4; q++) {
                    const float4 v = *(const float4*)(pfb + (q * 128 + tid) * 4);
                    p0 += v.x; p1 += v.y; p2 += v.z; p3 += v.w;
                }
                const float* tr = trig + tid * 8;
                const float s1 = tr[0], c1 = tr[1], s2 = tr[2], c2 = tr[3];
                const float w1v = tr[4], w2v = tr[5];
                const float sd = s1 * c2 - c1 * s2;
                const float cd = c1 * c2 + s1 * s2;
                const float dV1 = p0 * c1 - p1 * s1;
                const float dV2 = p2 * c2 - p3 * s2;
                const float dw = w2v - w1v;
                const float rhs1 = -w1v * w2v * sd - dV1 - w2v * sd * dw;
                const float rhs2 =  w1v * w2v * sd - dV2 - w1v * sd * dw;
                const float det = 2.0f - cd * cd;
                const float inv = __fdividef(1.0f, det);
                const float q1 = (rhs1 - cd * rhs2) * inv;
                const float q2 = (2.0f * rhs2 - cd * rhs1) * inv;
                reinterpret_cast<float4*>(out)[gidx] = make_float4(w1v, w2v, q1, q2);
            }
        }
        __syncthreads();
    }
}

extern "C" void kernel_launch(void* const* d_in, const int* in_sizes, int n_in,
                              void* d_out, int out_size)
{
    const float* X  = (const float*)d_in[0];
    const float* W1 = (const float*)d_in[1];
    const float* b1 = (const float*)d_in[2];
    const float* W2 = (const float*)d_in[3];
    const float* b2 = (const float*)d_in[4];
    const float* W3 = (const float*)d_in[5];
    float* out = (float*)d_out;
    const int B = in_sizes[0] / 4;

    cudaFuncSetAttribute(lnn_kernel,
                         cudaFuncAttributeMaxDynamicSharedMemorySize,
                         SMEM_TOTAL);
    lnn_kernel<<<296, NTHR, SMEM_TOTAL>>>(X, W1, b1, W2, b2, W3, out, B);
}

// round 14
// speedup vs baseline: 5.5529x; 1.0988x over previous
#include <cuda_runtime.h>
#include <cuda_fp16.h>
#include <cstdint>

#define NTHR 256

// ---- shared memory byte offsets ----
#define BB_HI 0                 // W2 [j][k] fp16 (both GEMMs), 32KB
#define H1_OF (32*1024)         // H1 tile [s][j] fp16, 128 rows, 32KB
#define G2_OF (64*1024)         // G2 tile [s][k] fp16, 128 rows, 32KB
#define OW1   (96*1024)         // 4*128 floats
#define OB1   (OW1 + 2048)
#define OB2   (OB1 + 512)
#define OW3   (OB2 + 512)
#define OTRIG (OW3 + 512)       // 128 * 8 floats = 4KB
#define OPF   (OTRIG + 128*8*4) // 4 * 128 * 4 floats = 8KB
#define SMEM_TOTAL (OPF + 4*128*4*4)

__device__ __forceinline__ uint32_t smem_u32(const void* p) {
    uint32_t a;
    asm("{ .reg .u64 t; cvta.to.shared.u64 t, %1; cvt.u32.u64 %0, t; }"
        : "=r"(a) : "l"(p));
    return a;
}
__device__ __forceinline__ float ftanh(float x) {
    float y;
    asm("tanh.approx.f32 %0, %1;" : "=f"(y) : "f"(x));
    return y;
}
// swizzled byte offset of 16B chunk (row r, chunk) in a [rows]x128 fp16 tile
__device__ __forceinline__ uint32_t swz(int r, int chunk) {
    return (uint32_t)((r << 8) + (((chunk ^ (r & 7)) & 15) << 4));
}
__device__ __forceinline__ uint32_t helem(int r, int c) {
    return swz(r, c >> 3) + ((c & 7) << 1);
}
__device__ __forceinline__ uint32_t packh2(float x0, float x1) {
    const __half2 h = __floats2half2_rn(x0, x1);
    return *(const uint32_t*)&h;
}
__device__ __forceinline__ void ldsm4(uint32_t& r0, uint32_t& r1,
                                      uint32_t& r2, uint32_t& r3, uint32_t a) {
    asm volatile("ldmatrix.sync.aligned.m8n8.x4.shared.b16 {%0,%1,%2,%3}, [%4];"
                 : "=r"(r0), "=r"(r1), "=r"(r2), "=r"(r3) : "r"(a));
}
__device__ __forceinline__ void ldsm4t(uint32_t& r0, uint32_t& r1,
                                       uint32_t& r2, uint32_t& r3, uint32_t a) {
    asm volatile("ldmatrix.sync.aligned.m8n8.x4.trans.shared.b16 {%0,%1,%2,%3}, [%4];"
                 : "=r"(r0), "=r"(r1), "=r"(r2), "=r"(r3) : "r"(a));
}
__device__ __forceinline__ void stsm4(uint32_t a, uint32_t r0, uint32_t r1,
                                      uint32_t r2, uint32_t r3) {
    asm volatile("stmatrix.sync.aligned.m8n8.x4.shared.b16 [%0], {%1,%2,%3,%4};"
                 :: "r"(a), "r"(r0), "r"(r1), "r"(r2), "r"(r3) : "memory");
}
__device__ __forceinline__ void mma16816(float d[4],
                                         uint32_t a0, uint32_t a1,
                                         uint32_t a2, uint32_t a3,
                                         uint32_t b0, uint32_t b1) {
    asm volatile(
        "mma.sync.aligned.m16n8k16.row.col.f32.f16.f16.f32 "
        "{%0,%1,%2,%3}, {%4,%5,%6,%7}, {%8,%9}, {%0,%1,%2,%3};"
        : "+f"(d[0]), "+f"(d[1]), "+f"(d[2]), "+f"(d[3])
        : "r"(a0), "r"(a1), "r"(a2), "r"(a3), "r"(b0), "r"(b1));
}

// D(128x128) = A(128x128) @ op(B); plain fp16 single term.
// 8 warps in 2x4 grid: warp computes m64 x n32 (mt=4).
// TRANSB: B memory [kdim][n]; else [n][kdim].
template <bool TRANSB>
__device__ __forceinline__ void gemm_tile(uint32_t sb, uint32_t Aoff, uint32_t Bo,
                                          int mbase, int nbase, int lane,
                                          float acc[4][4][4]) {
    #pragma unroll
    for (int mt = 0; mt < 4; mt++)
        #pragma unroll
        for (int nt = 0; nt < 4; nt++)
            #pragma unroll
            for (int e = 0; e < 4; e++) acc[mt][nt][e] = 0.0f;

    #pragma unroll
    for (int k = 0; k < 8; k++) {
        const int cb = k * 2;
        uint32_t bH[4][2];
        #pragma unroll
        for (int p = 0; p < 2; p++) {
            const int ntl   = 2 * p + ((lane >> 4) & 1);
            const int khalf = (lane >> 3) & 1;
            if (TRANSB) {
                const int r = k * 16 + khalf * 8 + (lane & 7);
                const uint32_t off = swz(r, (nbase + ntl * 8) >> 3);
                ldsm4t(bH[2*p][0], bH[2*p][1], bH[2*p+1][0], bH[2*p+1][1],
                       sb + Bo + off);
            } else {
                const int r = nbase + ntl * 8 + (lane & 7);
                const uint32_t off = swz(r, cb + khalf);
                ldsm4(bH[2*p][0], bH[2*p][1], bH[2*p+1][0], bH[2*p+1][1],
                      sb + Bo + off);
            }
        }
        #pragma unroll
        for (int mt = 0; mt < 4; mt++) {
            uint32_t aH[4];
            const int r = mbase + mt * 16 + (lane & 15);
            const uint32_t off = swz(r, cb + (lane >> 4));
            ldsm4(aH[0], aH[1], aH[2], aH[3], sb + Aoff + off);
            #pragma unroll
            for (int nt = 0; nt < 4; nt++)
                mma16816(acc[mt][nt], aH[0], aH[1], aH[2], aH[3],
                         bH[nt][0], bH[nt][1]);
        }
    }
}

__global__ void __launch_bounds__(NTHR, 2)
lnn_kernel(const float* __restrict__ X,
           const float* __restrict__ W1, const float* __restrict__ b1,
           const float* __restrict__ W2, const float* __restrict__ b2,
           const float* __restrict__ W3,
           float* __restrict__ out, int B)
{
    extern __shared__ char smem[];
    const uint32_t sb = smem_u32(smem);
    const int tid  = threadIdx.x;
    const int wid  = tid >> 5;
    const int lane = tid & 31;

    // ---- stage W2 fp16 (single [j][k] layout) ----
    for (int idx = tid; idx < 128 * 128; idx += NTHR) {
        const int j = idx >> 7, k = idx & 127;
        const __half h = __float2half_rn(W2[idx]);
        *(uint16_t*)(smem + BB_HI + helem(j, k)) = __half_as_ushort(h);
    }
    {
        float* w1s = (float*)(smem + OW1);
        for (int i = tid; i < 512; i += NTHR) w1s[i] = W1[i];
        float* d1 = (float*)(smem + OB1);
        float* d2 = (float*)(smem + OB2);
        float* d3 = (float*)(smem + OW3);
        for (int i = tid; i < 128; i += NTHR) {
            d1[i] = b1[i]; d2[i] = b2[i]; d3[i] = W3[i];
        }
    }
    __syncthreads();

    const float* w1p = (const float*)(smem + OW1);
    const float* b1p = (const float*)(smem + OB1);
    const float* b2p = (const float*)(smem + OB2);
    const float* w3p = (const float*)(smem + OW3);
    float* trig = (float*)(smem + OTRIG);
    float* pfb  = (float*)(smem + OPF);

    const int mg = wid >> 2, ng = wid & 3;     // 2 x 4 warp grid
    const int mbase = mg * 64, nbase = ng * 32;

    // lane-owned column indices (same for all mt/hf): c = nbase+nt*8+2*(lane&3)
    // hoisted per-lane constants for epilogues (loaded once, reused every tile)
    float b2v[8], w3v[8], w1a[8][4];
    #pragma unroll
    for (int nt = 0; nt < 4; nt++) {
        const int c = nbase + nt * 8 + 2 * (lane & 3);
        #pragma unroll
        for (int e = 0; e < 2; e++) {
            const int j = c + e;
            b2v[nt * 2 + e] = b2p[j];
            w3v[nt * 2 + e] = w3p[j];
            w1a[nt * 2 + e][0] = w1p[j];
            w1a[nt * 2 + e][1] = w1p[128 + j];
            w1a[nt * 2 + e][2] = w1p[256 + j];
            w1a[nt * 2 + e][3] = w1p[384 + j];
        }
    }

    const int nTiles = (B + 127) >> 7;         // 128-sample tiles
    for (int t = blockIdx.x; t < nTiles; t += gridDim.x) {
        // ---- 1. trig staging ----
        if (tid < 128) {
            const int g = (t << 7) + tid;
            if (g < B) {
                const float4 x = reinterpret_cast<const float4*>(X)[g];
                float s1, c1, s2, c2;
                __sincosf(x.x, &s1, &c1);
                __sincosf(x.y, &s2, &c2);
                float* tr = trig + tid * 8;
                tr[0] = s1; tr[1] = c1; tr[2] = s2; tr[3] = c2;
                tr[4] = x.z; tr[5] = x.w;
            }
        }
        __syncthreads();

        // ---- 2. layer 1: H1 = tanh(feat @ W1 + b1) -> H1 buf (fp16) ----
        {
            const int s = tid & 127;
            const int q = tid >> 7;            // 0..1, owns chunks q*8..q*8+7
            const float* tr = trig + s * 8;
            const float s1 = tr[0], c1 = tr[1], s2 = tr[2], c2 = tr[3];
            #pragma unroll
            for (int qq = 0; qq < 8; qq++) {
                const int cc = q * 8 + qq;
                uint32_t hw[4];
                #pragma unroll
                for (int p = 0; p < 4; p++) {
                    const int j = cc * 8 + p * 2;
                    float z0 = b1p[j], z1 = b1p[j + 1];
                    z0 = fmaf(s1, w1p[j], z0);       z1 = fmaf(s1, w1p[j + 1], z1);
                    z0 = fmaf(c1, w1p[128 + j], z0); z1 = fmaf(c1, w1p[129 + j], z1);
                    z0 = fmaf(s2, w1p[256 + j], z0); z1 = fmaf(s2, w1p[257 + j], z1);
                    z0 = fmaf(c2, w1p[384 + j], z0); z1 = fmaf(c2, w1p[385 + j], z1);
                    hw[p] = packh2(ftanh(z0), ftanh(z1));
                }
                const uint32_t off = swz(s, cc);
                *(uint4*)(smem + H1_OF + off) = make_uint4(hw[0], hw[1], hw[2], hw[3]);
            }
        }
        __syncthreads();

        // ---- 3. GEMM1: Z2 = H1 @ W2 (B via trans ldmatrix on [j][k]) ----
        float acc[4][4][4];
        gemm_tile<true>(sb, H1_OF, BB_HI, mbase, nbase, lane, acc);

        // ---- 4. epilogue 1: G2 = W3*(1-tanh(Z2+b2)^2) -> G2 buf (stmatrix) ----
        #pragma unroll
        for (int mt = 0; mt < 4; mt++)
            #pragma unroll
            for (int hf = 0; hf < 2; hf++) {
                uint32_t rr[4];
                #pragma unroll
                for (int nt = 0; nt < 4; nt++) {
                    const float z0 = acc[mt][nt][hf * 2]     + b2v[nt * 2];
                    const float z1 = acc[mt][nt][hf * 2 + 1] + b2v[nt * 2 + 1];
                    const float t0 = ftanh(z0), t1 = ftanh(z1);
                    const float g0 = w3v[nt * 2]     * (1.0f - t0 * t0);
                    const float g1 = w3v[nt * 2 + 1] * (1.0f - t1 * t1);
                    rr[nt] = packh2(g0, g1);
                }
                const int row = mbase + mt * 16 + hf * 8 + (lane & 7);
                const uint32_t addr =
                    sb + G2_OF + swz(row, (nbase >> 3) + (lane >> 3));
                stsm4(addr, rr[0], rr[1], rr[2], rr[3]);
            }
        __syncthreads();

        // ---- 5. GEMM2: G1pre = G2 @ W2^T (B non-trans on [j][k]) ----
        gemm_tile<false>(sb, G2_OF, BB_HI, mbase, nbase, lane, acc);

        // ---- 6. epilogue 2: h1 fragments via ldmatrix; pf_i = sum W1*g1 ----
        #pragma unroll
        for (int mt = 0; mt < 4; mt++)
            #pragma unroll
            for (int hf = 0; hf < 2; hf++) {
                const int lrow = mbase + mt * 16 + hf * 8 + (lane & 7);
                uint32_t hfrag[4];
                ldsm4(hfrag[0], hfrag[1], hfrag[2], hfrag[3],
                      sb + H1_OF + swz(lrow, (nbase >> 3) + (lane >> 3)));
                float pf0 = 0.f, pf1 = 0.f, pf2 = 0.f, pf3 = 0.f;
                #pragma unroll
                for (int nt = 0; nt < 4; nt++) {
                    const float2 fh = __half22float2(*(const __half2*)&hfrag[nt]);
                    const float hv[2] = {fh.x, fh.y};
                    #pragma unroll
                    for (int e = 0; e < 2; e++) {
                        const float pre = acc[mt][nt][hf * 2 + e];
                        const float h = hv[e];
                        const float g1 = (1.0f - h * h) * pre;
                        const float* wa = w1a[nt * 2 + e];
                        pf0 = fmaf(wa[0], g1, pf0); pf1 = fmaf(wa[1], g1, pf1);
                        pf2 = fmaf(wa[2], g1, pf2); pf3 = fmaf(wa[3], g1, pf3);
                    }
                }
                pf0 += __shfl_xor_sync(0xffffffffu, pf0, 1);
                pf1 += __shfl_xor_sync(0xffffffffu, pf1, 1);
                pf2 += __shfl_xor_sync(0xffffffffu, pf2, 1);
                pf3 += __shfl_xor_sync(0xffffffffu, pf3, 1);
                pf0 += __shfl_xor_sync(0xffffffffu, pf0, 2);
                pf1 += __shfl_xor_sync(0xffffffffu, pf1, 2);
                pf2 += __shfl_xor_sync(0xffffffffu, pf2, 2);
                pf3 += __shfl_xor_sync(0xffffffffu, pf3, 2);
                const int row = mbase + mt * 16 + (lane >> 2) + hf * 8;
                if ((lane & 3) == 0)
                    *(float4*)(pfb + (ng * 128 + row) * 4) =
                        make_float4(pf0, pf1, pf2, pf3);
            }
        __syncthreads();

        // ---- 7. combine partials + analytic closure + 2x2 solve ----
        if (tid < 128) {
            const int gidx = (t << 7) + tid;
            if (gidx < B) {
                float p0 = 0.f, p1 = 0.f, p2 = 0.f, p3 = 0.f;
                #pragma unroll
                for (int q = 0; q < 4; q++) {
                    const float4 v = *(const float4*)(pfb + (q * 128 + tid) * 4);
                    p0 += v.x; p1 += v.y; p2 += v.z; p3 += v.w;
                }
                const float* tr = trig + tid * 8;
                const float s1 = tr[0], c1 = tr[1], s2 = tr[2], c2 = tr[3];
                const float w1v = tr[4], w2v = tr[5];
                const float sd = s1 * c2 - c1 * s2;
                const float cd = c1 * c2 + s1 * s2;
                const float dV1 = p0 * c1 - p1 * s1;
                const float dV2 = p2 * c2 - p3 * s2;
                const float dw = w2v - w1v;
                const float rhs1 = -w1v * w2v * sd - dV1 - w2v * sd * dw;
                const float rhs2 =  w1v * w2v * sd - dV2 - w1v * sd * dw;
                const float det = 2.0f - cd * cd;
                const float inv = __fdividef(1.0f, det);
                const float q1 = (rhs1 - cd * rhs2) * inv;
                const float q2 = (2.0f * rhs2 - cd * rhs1) * inv;
                reinterpret_cast<float4*>(out)[gidx] = make_float4(w1v, w2v, q1, q2);
            }
        }
        __syncthreads();
    }
}

extern "C" void kernel_launch(void* const* d_in, const int* in_sizes, int n_in,
                              void* d_out, int out_size)
{
    const float* X  = (const float*)d_in[0];
    const float* W1 = (const float*)d_in[1];
    const float* b1 = (const float*)d_in[2];
    const float* W2 = (const float*)d_in[3];
    const float* b2 = (const float*)d_in[4];
    const float* W3 = (const float*)d_in[5];
    float* out = (float*)d_out;
    const int B = in_sizes[0] / 4;

    cudaFuncSetAttribute(lnn_kernel,
                         cudaFuncAttributeMaxDynamicSharedMemorySize,
                         SMEM_TOTAL);
    lnn_kernel<<<296, NTHR, SMEM_TOTAL>>>(X, W1, b1, W2, b2, W3, out, B);
}